// round 1
// baseline (speedup 1.0000x reference)
#include <cuda_runtime.h>

#define Bd   4096
#define Sd   512
#define Ad   64
#define H1d  1024
#define H2d  512
#define EPSf 1e-8f
#define TK   16

typedef unsigned long long ull;

// scratch (device globals: no allocation allowed)
__device__ float g_G[Bd * H1d];      // 16 MB: G[b][o] = states[b,:] . W1[o,:512]
__device__ float g_AWT[H1d * Ad];    // 256 KB: AWT[o*64+a] = W1[o,512+a]
__device__ float g_invn[Bd];         // 1/(sqrt(|s|^2+1)+eps)

__device__ __forceinline__ ull pk2(float lo, float hi) {
    ull r;
    asm("mov.b64 %0, {%1, %2};" : "=l"(r)
        : "r"(__float_as_uint(lo)), "r"(__float_as_uint(hi)));
    return r;
}
__device__ __forceinline__ void upk2(ull v, float& lo, float& hi) {
    unsigned a, b;
    asm("mov.b64 {%0, %1}, %2;" : "=r"(a), "=r"(b) : "l"(v));
    lo = __uint_as_float(a); hi = __uint_as_float(b);
}
__device__ __forceinline__ ull ffma2(ull a, ull b, ull c) {
    ull d;
    asm("fma.rn.f32x2 %0, %1, %2, %3;" : "=l"(d) : "l"(a), "l"(b), "l"(c));
    return d;
}

// ---------------------------------------------------------------------------
// Prep: gather action columns of W1 into [o][a] layout (coalesced later)
// ---------------------------------------------------------------------------
__global__ void k_prep_awt(const float* __restrict__ W1) {
    int i = blockIdx.x * 256 + threadIdx.x;
    if (i < H1d * Ad) {
        int o = i >> 6, a = i & 63;
        g_AWT[i] = W1[o * 576 + 512 + a];
    }
}

// ---------------------------------------------------------------------------
// Prep: inv_n[b] = 1/(sqrt(|states_b|^2 + 1) + eps)   (one warp per row)
// ---------------------------------------------------------------------------
__global__ void k_invn(const float* __restrict__ states) {
    int w    = (blockIdx.x * blockDim.x + threadIdx.x) >> 5;
    int lane = threadIdx.x & 31;
    if (w >= Bd) return;
    const float* s = states + w * Sd;
    float acc = 0.f;
#pragma unroll 4
    for (int j = lane; j < Sd; j += 32) { float v = s[j]; acc += v * v; }
#pragma unroll
    for (int off = 16; off; off >>= 1) acc += __shfl_xor_sync(0xffffffffu, acc, off);
    if (lane == 0) g_invn[w] = 1.f / (sqrtf(acc + 1.f) + EPSf);
}

// ---------------------------------------------------------------------------
// G[b][o] = sum_s states[b,s] * W1[o,s]   (4096x1024, K=512)
// 128x128 tile, 256 threads, 8x8 microtile, f32x2 FMAs, double-buffered smem
// ---------------------------------------------------------------------------
__global__ void __launch_bounds__(256) k_gemmG(const float* __restrict__ states,
                                               const float* __restrict__ W1) {
    __shared__ __align__(16) float As[2][TK][128];
    __shared__ __align__(16) float Bs[2][TK][128];

    int b0  = (blockIdx.x >> 3) * 128;
    int o0  = (blockIdx.x & 7) * 128;
    int tid = threadIdx.x;
    int tm  = tid >> 4, tn = tid & 15;

    ull acc[4][8];
#pragma unroll
    for (int i = 0; i < 4; i++)
#pragma unroll
        for (int j = 0; j < 8; j++) acc[i][j] = 0ull;

    auto loadTile = [&](int c, int buf) {
        int k0 = c * TK;
#pragma unroll
        for (int it = 0; it < 2; it++) {
            int e = tid + it * 256;
            int r = e >> 2, kq = (e & 3) * 4;
            float4 va = *(const float4*)&states[(b0 + r) * Sd + k0 + kq];
            As[buf][kq + 0][r] = va.x; As[buf][kq + 1][r] = va.y;
            As[buf][kq + 2][r] = va.z; As[buf][kq + 3][r] = va.w;
            float4 vb = *(const float4*)&W1[(o0 + r) * 576 + k0 + kq];
            Bs[buf][kq + 0][r] = vb.x; Bs[buf][kq + 1][r] = vb.y;
            Bs[buf][kq + 2][r] = vb.z; Bs[buf][kq + 3][r] = vb.w;
        }
    };

    loadTile(0, 0);
    __syncthreads();
    const int NC = Sd / TK;  // 32
    for (int c = 0; c < NC; c++) {
        int buf = c & 1;
        if (c + 1 < NC) loadTile(c + 1, buf ^ 1);
#pragma unroll
        for (int kk = 0; kk < TK; kk++) {
            ull a2[4];
            const ull* ap = (const ull*)&As[buf][kk][tm * 8];
#pragma unroll
            for (int i = 0; i < 4; i++) a2[i] = ap[i];
            float4 bv0 = *(const float4*)&Bs[buf][kk][tn * 8];
            float4 bv1 = *(const float4*)&Bs[buf][kk][tn * 8 + 4];
            ull b2r[8];
            b2r[0] = pk2(bv0.x, bv0.x); b2r[1] = pk2(bv0.y, bv0.y);
            b2r[2] = pk2(bv0.z, bv0.z); b2r[3] = pk2(bv0.w, bv0.w);
            b2r[4] = pk2(bv1.x, bv1.x); b2r[5] = pk2(bv1.y, bv1.y);
            b2r[6] = pk2(bv1.z, bv1.z); b2r[7] = pk2(bv1.w, bv1.w);
#pragma unroll
            for (int i = 0; i < 4; i++)
#pragma unroll
                for (int j = 0; j < 8; j++)
                    acc[i][j] = ffma2(a2[i], b2r[j], acc[i][j]);
        }
        __syncthreads();
    }
    // store: rows m0, m0+1 each as 2 float4
#pragma unroll
    for (int i = 0; i < 4; i++) {
        float lo[8], hi[8];
#pragma unroll
        for (int j = 0; j < 8; j++) upk2(acc[i][j], lo[j], hi[j]);
        int m0 = b0 + tm * 8 + i * 2;
        float* p0 = &g_G[(m0 + 0) * H1d + o0 + tn * 8];
        float* p1 = &g_G[(m0 + 1) * H1d + o0 + tn * 8];
        *(float4*)p0       = make_float4(lo[0], lo[1], lo[2], lo[3]);
        *(float4*)(p0 + 4) = make_float4(lo[4], lo[5], lo[6], lo[7]);
        *(float4*)p1       = make_float4(hi[0], hi[1], hi[2], hi[3]);
        *(float4*)(p1 + 4) = make_float4(hi[4], hi[5], hi[6], hi[7]);
    }
}

// ---------------------------------------------------------------------------
// Main fused kernel. Row index r = b*64 + a (== output index in [B,A]).
// Each CTA: 128 rows (= 2 b values x 64 actions), K = 1024, N = 512 (4 tiles).
//   pass 1: row norms of h1 (recompute h1 from G, AWT, inv_n)
//   pass 2: GEMM with A generated on the fly into smem; epilogue fuses
//           +b2, ReLU, dot with Wq, half-warp shuffle reduction -> q partials.
// ---------------------------------------------------------------------------
__global__ void __launch_bounds__(256) k_main(const float* __restrict__ b1,
                                              const float* __restrict__ W2,
                                              const float* __restrict__ b2,
                                              const float* __restrict__ Wq,
                                              const float* __restrict__ bq,
                                              float* __restrict__ out) {
    __shared__ __align__(16) float As[2][TK][128];
    __shared__ __align__(16) float Bs[2][TK][128];
    __shared__ __align__(16) float Gs[2][H1d];
    __shared__ __align__(16) float b1s[H1d];
    __shared__ float invn_s[2];
    __shared__ float rinv_s[128];

    int r0  = blockIdx.x * 128;   // first row of tile
    int b0  = r0 >> 6;            // first batch index (tile covers b0, b0+1)
    int tid = threadIdx.x;
    int tm  = tid >> 4, tn = tid & 15;

    // stage G rows + b1 + inv_n
    for (int i = tid; i < 2 * H1d; i += 256)
        Gs[i >> 10][i & 1023] = g_G[(b0 + (i >> 10)) * H1d + (i & 1023)];
    for (int i = tid; i < H1d; i += 256) b1s[i] = b1[i];
    if (tid < 2) invn_s[tid] = g_invn[b0 + tid];
    __syncthreads();

    // -------- pass 1: row norms of h1 (2 threads per row, 512 elems each)
    {
        int rl = tid >> 1, half = tid & 1;
        int bl = rl >> 6, a = rl & 63;
        float inv = invn_s[bl];
        float ss  = 0.f;
        int obase = half * 512;
#pragma unroll 8
        for (int j = 0; j < 512; j++) {
            int o  = obase + j;
            float h = fmaf(Gs[bl][o] + g_AWT[o * 64 + a], inv, b1s[o]);
            h = fmaxf(h, 0.f);
            ss += h * h;
        }
        float* tmp = &As[0][0][0];
        tmp[tid] = ss;
        __syncthreads();
        if (tid < 128)
            rinv_s[tid] = 1.f / (sqrtf(tmp[2 * tid] + tmp[2 * tid + 1]) + EPSf);
        __syncthreads();
    }

    // -------- pass 2: GEMM over 4 N-tiles
    float qreg[8];
#pragma unroll
    for (int i = 0; i < 8; i++) qreg[i] = 0.f;

    auto genA = [&](int c, int buf) {
        int k0 = c * TK;
#pragma unroll
        for (int it = 0; it < 8; it++) {
            int e = tid + it * 256;
            int k = e >> 7, m = e & 127;
            int o = k0 + k;
            float h = fmaf(Gs[m >> 6][o] + g_AWT[o * 64 + (m & 63)],
                           invn_s[m >> 6], b1s[o]);
            As[buf][k][m] = fmaxf(h, 0.f) * rinv_s[m];
        }
    };
    auto loadB = [&](int c, int buf, int n0) {
        int k0 = c * TK;
#pragma unroll
        for (int it = 0; it < 2; it++) {
            int e = tid + it * 256;
            int n = e >> 2, kq = (e & 3) * 4;
            float4 v = *(const float4*)&W2[(n0 + n) * H1d + k0 + kq];
            Bs[buf][kq + 0][n] = v.x; Bs[buf][kq + 1][n] = v.y;
            Bs[buf][kq + 2][n] = v.z; Bs[buf][kq + 3][n] = v.w;
        }
    };

    for (int nt = 0; nt < 4; nt++) {
        int n0 = nt * 128;
        ull acc[4][8];
#pragma unroll
        for (int i = 0; i < 4; i++)
#pragma unroll
            for (int j = 0; j < 8; j++) acc[i][j] = 0ull;

        genA(0, 0);
        loadB(0, 0, n0);
        __syncthreads();
        const int NC = H1d / TK;  // 64
        for (int c = 0; c < NC; c++) {
            int buf = c & 1;
            if (c + 1 < NC) { genA(c + 1, buf ^ 1); loadB(c + 1, buf ^ 1, n0); }
#pragma unroll
            for (int kk = 0; kk < TK; kk++) {
                ull a2[4];
                const ull* ap = (const ull*)&As[buf][kk][tm * 8];
#pragma unroll
                for (int i = 0; i < 4; i++) a2[i] = ap[i];
                float4 bv0 = *(const float4*)&Bs[buf][kk][tn * 8];
                float4 bv1 = *(const float4*)&Bs[buf][kk][tn * 8 + 4];
                ull b2r[8];
                b2r[0] = pk2(bv0.x, bv0.x); b2r[1] = pk2(bv0.y, bv0.y);
                b2r[2] = pk2(bv0.z, bv0.z); b2r[3] = pk2(bv0.w, bv0.w);
                b2r[4] = pk2(bv1.x, bv1.x); b2r[5] = pk2(bv1.y, bv1.y);
                b2r[6] = pk2(bv1.z, bv1.z); b2r[7] = pk2(bv1.w, bv1.w);
#pragma unroll
                for (int i = 0; i < 4; i++)
#pragma unroll
                    for (int j = 0; j < 8; j++)
                        acc[i][j] = ffma2(a2[i], b2r[j], acc[i][j]);
            }
            __syncthreads();
        }

        // epilogue for this N-tile: z2 = acc + b2 ; relu ; dot with Wq
        float wqv[8], b2v[8];
#pragma unroll
        for (int j = 0; j < 8; j++) {
            wqv[j] = Wq[n0 + tn * 8 + j];
            b2v[j] = b2[n0 + tn * 8 + j];
        }
        float part[8];
#pragma unroll
        for (int i = 0; i < 8; i++) part[i] = 0.f;
#pragma unroll
        for (int i = 0; i < 4; i++) {
#pragma unroll
            for (int j = 0; j < 8; j++) {
                float lo, hi;
                upk2(acc[i][j], lo, hi);
                float zl = fmaxf(lo + b2v[j], 0.f);
                float zh = fmaxf(hi + b2v[j], 0.f);
                part[2 * i + 0] += zl * wqv[j];
                part[2 * i + 1] += zh * wqv[j];
            }
        }
        // reduce across the 16 tn threads (lanes 0-15 / 16-31 of the warp)
#pragma unroll
        for (int off = 8; off; off >>= 1)
#pragma unroll
            for (int i = 0; i < 8; i++)
                part[i] += __shfl_xor_sync(0xffffffffu, part[i], off);
        if (tn == 0)
#pragma unroll
            for (int i = 0; i < 8; i++) qreg[i] += part[i];
    }

    if (tn == 0) {
        float bqv = bq[0];
#pragma unroll
        for (int i = 0; i < 8; i++)
            out[r0 + tm * 8 + i] = qreg[i] + bqv;
    }
}

// ---------------------------------------------------------------------------
extern "C" void kernel_launch(void* const* d_in, const int* in_sizes, int n_in,
                              void* d_out, int out_size) {
    const float* states = (const float*)d_in[0];
    const float* W1     = (const float*)d_in[1];
    const float* b1     = (const float*)d_in[2];
    const float* W2     = (const float*)d_in[3];
    const float* b2     = (const float*)d_in[4];
    const float* Wq     = (const float*)d_in[5];
    const float* bq     = (const float*)d_in[6];
    float* out = (float*)d_out;

    k_prep_awt<<<(H1d * Ad + 255) / 256, 256>>>(W1);
    k_invn<<<Bd / 8, 256>>>(states);
    k_gemmG<<<(Bd / 128) * (H1d / 128), 256>>>(states, W1);
    k_main<<<(Bd * Ad) / 128, 256>>>(b1, W2, b2, Wq, bq, out);
}

// round 4
// speedup vs baseline: 2.6038x; 2.6038x over previous
#include <cuda_runtime.h>
#include <cuda_bf16.h>

#define Bd   4096
#define Sd   512
#define Ad   64
#define H1d  1024
#define H2d  512
#define EPSf 1e-8f
#define TK   16

typedef unsigned long long ull;
typedef unsigned int u32;

// ------------------------- device scratch (no allocs allowed) --------------
__device__ float g_G[Bd * H1d];              // Gp[b][o] = G*invn[b] + b1[o]
__device__ float g_AWT[H1d * Ad];            // [o][a] layout
__device__ float g_invn[Bd];
__device__ __nv_bfloat16 g_W2hi[H2d * H1d];
__device__ __nv_bfloat16 g_W2lo[H2d * H1d];

// ------------------------- helpers -----------------------------------------
__device__ __forceinline__ u32 smem_u32(const void* p) {
    u32 a;
    asm("{ .reg .u64 t; cvta.to.shared.u64 t, %1; cvt.u32.u64 %0, t; }"
        : "=r"(a) : "l"(p));
    return a;
}
__device__ __forceinline__ ull pk2(float lo, float hi) {
    ull r;
    asm("mov.b64 %0, {%1, %2};" : "=l"(r)
        : "r"(__float_as_uint(lo)), "r"(__float_as_uint(hi)));
    return r;
}
__device__ __forceinline__ void upk2(ull v, float& lo, float& hi) {
    unsigned a, b;
    asm("mov.b64 {%0, %1}, %2;" : "=r"(a), "=r"(b) : "l"(v));
    lo = __uint_as_float(a); hi = __uint_as_float(b);
}
__device__ __forceinline__ ull ffma2(ull a, ull b, ull c) {
    ull d;
    asm("fma.rn.f32x2 %0, %1, %2, %3;" : "=l"(d) : "l"(a), "l"(b), "l"(c));
    return d;
}
// pack two f32 into bf16x2 (lo -> low 16 bits)
__device__ __forceinline__ u32 pkbf(float lo, float hi) {
    u32 r;
    asm("cvt.rn.bf16x2.f32 %0, %1, %2;" : "=r"(r) : "f"(hi), "f"(lo));
    return r;
}
__device__ __forceinline__ float bflo2f(u32 q) { return __uint_as_float(q << 16); }
__device__ __forceinline__ float bfhi2f(u32 q) { return __uint_as_float(q & 0xffff0000u); }

__device__ __forceinline__ void cpasync16(u32 dst, const void* src) {
    asm volatile("cp.async.cg.shared.global [%0], [%1], 16;"
                 :: "r"(dst), "l"(src) : "memory");
}
__device__ __forceinline__ void ldm4(u32* r, u32 addr) {
    asm volatile("ldmatrix.sync.aligned.m8n8.x4.shared.b16 {%0,%1,%2,%3}, [%4];"
                 : "=r"(r[0]), "=r"(r[1]), "=r"(r[2]), "=r"(r[3]) : "r"(addr));
}
__device__ __forceinline__ void mma16816(float* c, const u32* a, u32 b0, u32 b1) {
    asm volatile(
        "mma.sync.aligned.m16n8k16.row.col.f32.bf16.bf16.f32 "
        "{%0,%1,%2,%3}, {%4,%5,%6,%7}, {%8,%9}, {%0,%1,%2,%3};"
        : "+f"(c[0]), "+f"(c[1]), "+f"(c[2]), "+f"(c[3])
        : "r"(a[0]), "r"(a[1]), "r"(a[2]), "r"(a[3]), "r"(b0), "r"(b1));
}

// ---------------------------------------------------------------------------
// Prep kernels
// ---------------------------------------------------------------------------
__global__ void k_prep_awt(const float* __restrict__ W1) {
    int i = blockIdx.x * 256 + threadIdx.x;
    if (i < H1d * Ad) {
        int o = i >> 6, a = i & 63;
        g_AWT[i] = W1[o * 576 + 512 + a];
    }
}
__global__ void k_prepW2(const float* __restrict__ W2) {
    int i = blockIdx.x * 256 + threadIdx.x;
    if (i < H2d * H1d) {
        float v = W2[i];
        __nv_bfloat16 h = __float2bfloat16(v);
        g_W2hi[i] = h;
        g_W2lo[i] = __float2bfloat16(v - __bfloat162float(h));
    }
}
__global__ void k_invn(const float* __restrict__ states) {
    int w    = (blockIdx.x * blockDim.x + threadIdx.x) >> 5;
    int lane = threadIdx.x & 31;
    if (w >= Bd) return;
    const float* s = states + w * Sd;
    float acc = 0.f;
#pragma unroll 4
    for (int j = lane; j < Sd; j += 32) { float v = s[j]; acc += v * v; }
#pragma unroll
    for (int off = 16; off; off >>= 1) acc += __shfl_xor_sync(0xffffffffu, acc, off);
    if (lane == 0) g_invn[w] = 1.f / (sqrtf(acc + 1.f) + EPSf);
}

// ---------------------------------------------------------------------------
// Gp[b][o] = (states[b,:].W1[o,:512]) * invn[b] + b1[o]
// ---------------------------------------------------------------------------
__global__ void __launch_bounds__(256) k_gemmG(const float* __restrict__ states,
                                               const float* __restrict__ W1,
                                               const float* __restrict__ b1) {
    __shared__ __align__(16) float As[2][TK][128];
    __shared__ __align__(16) float Bs[2][TK][128];

    int b0  = (blockIdx.x >> 3) * 128;
    int o0  = (blockIdx.x & 7) * 128;
    int tid = threadIdx.x;
    int tm  = tid >> 4, tn = tid & 15;

    ull acc[4][8];
#pragma unroll
    for (int i = 0; i < 4; i++)
#pragma unroll
        for (int j = 0; j < 8; j++) acc[i][j] = 0ull;

    auto loadTile = [&](int c, int buf) {
        int k0 = c * TK;
#pragma unroll
        for (int it = 0; it < 2; it++) {
            int e = tid + it * 256;
            int r = e >> 2, kq = (e & 3) * 4;
            float4 va = *(const float4*)&states[(b0 + r) * Sd + k0 + kq];
            As[buf][kq + 0][r] = va.x; As[buf][kq + 1][r] = va.y;
            As[buf][kq + 2][r] = va.z; As[buf][kq + 3][r] = va.w;
            float4 vb = *(const float4*)&W1[(o0 + r) * 576 + k0 + kq];
            Bs[buf][kq + 0][r] = vb.x; Bs[buf][kq + 1][r] = vb.y;
            Bs[buf][kq + 2][r] = vb.z; Bs[buf][kq + 3][r] = vb.w;
        }
    };

    loadTile(0, 0);
    __syncthreads();
    const int NC = Sd / TK;
    for (int c = 0; c < NC; c++) {
        int buf = c & 1;
        if (c + 1 < NC) loadTile(c + 1, buf ^ 1);
#pragma unroll
        for (int kk = 0; kk < TK; kk++) {
            ull a2[4];
            const ull* ap = (const ull*)&As[buf][kk][tm * 8];
#pragma unroll
            for (int i = 0; i < 4; i++) a2[i] = ap[i];
            float4 bv0 = *(const float4*)&Bs[buf][kk][tn * 8];
            float4 bv1 = *(const float4*)&Bs[buf][kk][tn * 8 + 4];
            ull b2r[8];
            b2r[0] = pk2(bv0.x, bv0.x); b2r[1] = pk2(bv0.y, bv0.y);
            b2r[2] = pk2(bv0.z, bv0.z); b2r[3] = pk2(bv0.w, bv0.w);
            b2r[4] = pk2(bv1.x, bv1.x); b2r[5] = pk2(bv1.y, bv1.y);
            b2r[6] = pk2(bv1.z, bv1.z); b2r[7] = pk2(bv1.w, bv1.w);
#pragma unroll
            for (int i = 0; i < 4; i++)
#pragma unroll
                for (int j = 0; j < 8; j++)
                    acc[i][j] = ffma2(a2[i], b2r[j], acc[i][j]);
        }
        __syncthreads();
    }

    float4 b1a = *(const float4*)&b1[o0 + tn * 8];
    float4 b1b = *(const float4*)&b1[o0 + tn * 8 + 4];
    float bb[8] = {b1a.x, b1a.y, b1a.z, b1a.w, b1b.x, b1b.y, b1b.z, b1b.w};
#pragma unroll
    for (int i = 0; i < 4; i++) {
        int m0 = b0 + tm * 8 + i * 2;
        float inv0 = g_invn[m0], inv1 = g_invn[m0 + 1];
        float lo[8], hi[8];
#pragma unroll
        for (int j = 0; j < 8; j++) {
            upk2(acc[i][j], lo[j], hi[j]);
            lo[j] = fmaf(lo[j], inv0, bb[j]);
            hi[j] = fmaf(hi[j], inv1, bb[j]);
        }
        float* p0 = &g_G[(m0 + 0) * H1d + o0 + tn * 8];
        float* p1 = &g_G[(m0 + 1) * H1d + o0 + tn * 8];
        *(float4*)p0       = make_float4(lo[0], lo[1], lo[2], lo[3]);
        *(float4*)(p0 + 4) = make_float4(lo[4], lo[5], lo[6], lo[7]);
        *(float4*)p1       = make_float4(hi[0], hi[1], hi[2], hi[3]);
        *(float4*)(p1 + 4) = make_float4(hi[4], hi[5], hi[6], hi[7]);
    }
}

// ---------------------------------------------------------------------------
// Main fused kernel: mma.sync bf16 hi/lo split GEMM
//   per CTA: M=128 rows (2 batch x 64 actions), N=512 in 4 passes of 128,
//   K=1024 in 16 chunks of 64, 2-stage cp.async pipeline.
// ---------------------------------------------------------------------------
#define SOFF_GPS   0        // 2*1024 f32   (8192 B)
#define SOFF_B2    8192     // 512 f32
#define SOFF_WQ    10240    // 512 f32
#define SOFF_SS    12288    // 256 f32 (reused as q cross-warp buffer)
#define SOFF_RINV  13312    // 128 f32
#define SOFF_INVN  13824    // 2 f32
#define SOFF_STG   14336
#define STG_BYTES  65536
#define AHI_OFF    0
#define ALO_OFF    16384
#define BHI_OFF    32768
#define BLO_OFF    49152
#define SMEM_TOTAL (SOFF_STG + 2 * STG_BYTES)   // 145408 B

__global__ void __launch_bounds__(256, 1)
k_main(const float* __restrict__ b2, const float* __restrict__ Wq,
       const float* __restrict__ bq, float* __restrict__ out) {
    extern __shared__ __align__(1024) char smem[];
    u32 sb = smem_u32(smem);
    int tid = threadIdx.x;
    int wid = tid >> 5, lane = tid & 31;
    int warp_m = wid >> 1, warp_n = wid & 1;
    int r0 = blockIdx.x * 128, b0 = r0 >> 6;

    float* Gps   = (float*)(smem + SOFF_GPS);
    float* b2s   = (float*)(smem + SOFF_B2);
    float* wqs   = (float*)(smem + SOFF_WQ);
    float* sss   = (float*)(smem + SOFF_SS);
    float* rinvs = (float*)(smem + SOFF_RINV);
    float* invns = (float*)(smem + SOFF_INVN);

    for (int i = tid; i < 2 * H1d; i += 256)
        Gps[i] = g_G[(b0 + (i >> 10)) * H1d + (i & 1023)];
    for (int i = tid; i < H2d; i += 256) { b2s[i] = b2[i]; wqs[i] = Wq[i]; }
    if (tid < 2) invns[tid] = g_invn[b0 + tid];
    __syncthreads();

    // producer identity: each thread owns row m, half of k
    int m = tid >> 1, half = tid & 1;
    int a = m & 63, blc = m >> 6;
    float inv = invns[blc];
    const float* gpr = Gps + blc * H1d;
    float ss = 0.f;

    // A-tile generator: h1 for (chunk c) -> bf16 hi/lo into stage buf
    auto genA = [&](int pass, int c, int buf) {
        char* stg = smem + SOFF_STG + buf * STG_BYTES;
        int ob = c * 64 + half * 32;
        u32 offb = (u32)(m * 128);
        int mx = m & 7;
#pragma unroll
        for (int g4 = 0; g4 < 4; g4++) {
            int o = ob + g4 * 8;
            float h[8];
#pragma unroll
            for (int j = 0; j < 8; j++) {
                float w = g_AWT[(o + j) * 64 + a];
                h[j] = fmaxf(fmaf(inv, w, gpr[o + j]), 0.f);
            }
            if (pass == 0) {
                float s2 = 0.f;
#pragma unroll
                for (int j = 0; j < 8; j++) s2 = fmaf(h[j], h[j], s2);
                ss += s2;
            }
            u32 q0 = pkbf(h[0], h[1]), q1 = pkbf(h[2], h[3]);
            u32 q2 = pkbf(h[4], h[5]), q3 = pkbf(h[6], h[7]);
            u32 off = offb + (u32)((((half * 4 + g4) ^ mx)) << 4);
            *(uint4*)(stg + AHI_OFF + off) = make_uint4(q0, q1, q2, q3);
            u32 l0 = pkbf(h[0] - bflo2f(q0), h[1] - bfhi2f(q0));
            u32 l1 = pkbf(h[2] - bflo2f(q1), h[3] - bfhi2f(q1));
            u32 l2 = pkbf(h[4] - bflo2f(q2), h[5] - bfhi2f(q2));
            u32 l3 = pkbf(h[6] - bflo2f(q3), h[7] - bfhi2f(q3));
            *(uint4*)(stg + ALO_OFF + off) = make_uint4(l0, l1, l2, l3);
        }
    };
    // B-tile loader (cp.async): W2 hi/lo rows [pass*128 .. +128), k chunk c
    auto loadB = [&](int pass, int c, int buf) {
        u32 bh = sb + SOFF_STG + buf * STG_BYTES + BHI_OFF;
        u32 bl = bh + (BLO_OFF - BHI_OFF);
        const __nv_bfloat16* w2h = g_W2hi + (size_t)(pass * 128) * H1d + c * 64;
        const __nv_bfloat16* w2l = g_W2lo + (size_t)(pass * 128) * H1d + c * 64;
#pragma unroll
        for (int i = 0; i < 4; i++) {
            int G = tid + i * 256; int r = G >> 3, g = G & 7;
            u32 off = (u32)(r * 128 + ((g ^ (r & 7)) << 4));
            cpasync16(bh + off, w2h + (size_t)r * H1d + g * 8);
        }
#pragma unroll
        for (int i = 0; i < 4; i++) {
            int G = tid + i * 256; int r = G >> 3, g = G & 7;
            u32 off = (u32)(r * 128 + ((g ^ (r & 7)) << 4));
            cpasync16(bl + off, w2l + (size_t)r * H1d + g * 8);
        }
        asm volatile("cp.async.commit_group;" ::: "memory");
    };

    int lt = lane & 15, lh = lane >> 4;
    float qacc[4] = {0.f, 0.f, 0.f, 0.f};

    for (int pass = 0; pass < 4; pass++) {
        float acc[2][8][4];
#pragma unroll
        for (int i = 0; i < 2; i++)
#pragma unroll
            for (int j = 0; j < 8; j++)
#pragma unroll
                for (int k = 0; k < 4; k++) acc[i][j][k] = 0.f;

        genA(pass, 0, 0);
        loadB(pass, 0, 0);
        asm volatile("cp.async.wait_group 0;" ::: "memory");
        __syncthreads();

        for (int c = 0; c < 16; c++) {
            int buf = c & 1;
            if (c + 1 < 16) { genA(pass, c + 1, buf ^ 1); loadB(pass, c + 1, buf ^ 1); }

            // ---- mma on stage buf ----
            u32 abase = sb + SOFF_STG + buf * STG_BYTES;
#pragma unroll
            for (int ks = 0; ks < 4; ks++) {
                u32 ah[2][4], al[2][4], bhf[4][4], blf[4][4];
#pragma unroll
                for (int mt = 0; mt < 2; mt++) {
                    int row = warp_m * 32 + mt * 16 + lt;
                    u32 off = (u32)(row * 128 + (((ks * 2 + lh) ^ (row & 7)) << 4));
                    ldm4(ah[mt], abase + AHI_OFF + off);
                    ldm4(al[mt], abase + ALO_OFF + off);
                }
#pragma unroll
                for (int bt = 0; bt < 4; bt++) {
                    int row = warp_n * 64 + bt * 16 + lt;
                    u32 off = (u32)(row * 128 + (((ks * 2 + lh) ^ (row & 7)) << 4));
                    ldm4(bhf[bt], abase + BHI_OFF + off);
                    ldm4(blf[bt], abase + BLO_OFF + off);
                }
#pragma unroll
                for (int mt = 0; mt < 2; mt++)
#pragma unroll
                    for (int nt = 0; nt < 8; nt++) {
                        int bt = nt >> 1, s = nt & 1;
                        float* cc = acc[mt][nt];
                        mma16816(cc, ah[mt], bhf[bt][s], bhf[bt][s + 2]);
                        mma16816(cc, ah[mt], blf[bt][s], blf[bt][s + 2]);
                        mma16816(cc, al[mt], bhf[bt][s], bhf[bt][s + 2]);
                    }
            }
            asm volatile("cp.async.wait_group 0;" ::: "memory");
            __syncthreads();
        }

        if (pass == 0) {
            sss[tid] = ss;
            __syncthreads();
            if (tid < 128)
                rinvs[tid] = 1.f / (sqrtf(sss[2 * tid] + sss[2 * tid + 1]) + EPSf);
            __syncthreads();
        }

        // ---- epilogue: q += relu(acc * rinv + b2) * Wq ----
#pragma unroll
        for (int mt = 0; mt < 2; mt++) {
            int rlo = warp_m * 32 + mt * 16 + (lane >> 2);
            float rv0 = rinvs[rlo], rv1 = rinvs[rlo + 8];
#pragma unroll
            for (int nt = 0; nt < 8; nt++) {
                int n = pass * 128 + warp_n * 64 + nt * 8 + (lane & 3) * 2;
                float bb0 = b2s[n], bb1 = b2s[n + 1];
                float w0 = wqs[n], w1 = wqs[n + 1];
                const float* cc = acc[mt][nt];
                qacc[mt * 2 + 0] += fmaxf(fmaf(cc[0], rv0, bb0), 0.f) * w0 +
                                    fmaxf(fmaf(cc[1], rv0, bb1), 0.f) * w1;
                qacc[mt * 2 + 1] += fmaxf(fmaf(cc[2], rv1, bb0), 0.f) * w0 +
                                    fmaxf(fmaf(cc[3], rv1, bb1), 0.f) * w1;
            }
        }
    }

    // reduce q over the 4 lanes of each quad
#pragma unroll
    for (int off = 1; off <= 2; off <<= 1)
#pragma unroll
        for (int i = 0; i < 4; i++)
            qacc[i] += __shfl_xor_sync(0xffffffffu, qacc[i], off);

    __syncthreads();          // sss region reuse
    if ((lane & 3) == 0) {
#pragma unroll
        for (int mt = 0; mt < 2; mt++)
#pragma unroll
            for (int hh = 0; hh < 2; hh++) {
                int row = warp_m * 32 + mt * 16 + hh * 8 + (lane >> 2);
                sss[row * 2 + warp_n] = qacc[mt * 2 + hh];
            }
    }
    __syncthreads();
    if (tid < 128)
        out[r0 + tid] = sss[tid * 2] + sss[tid * 2 + 1] + __ldg(bq);
}

// ---------------------------------------------------------------------------
extern "C" void kernel_launch(void* const* d_in, const int* in_sizes, int n_in,
                              void* d_out, int out_size) {
    const float* states = (const float*)d_in[0];
    const float* W1     = (const float*)d_in[1];
    const float* b1     = (const float*)d_in[2];
    const float* W2     = (const float*)d_in[3];
    const float* b2     = (const float*)d_in[4];
    const float* Wq     = (const float*)d_in[5];
    const float* bq     = (const float*)d_in[6];
    float* out = (float*)d_out;

    cudaFuncSetAttribute((const void*)k_main,
                         cudaFuncAttributeMaxDynamicSharedMemorySize, SMEM_TOTAL);

    k_invn<<<Bd / 8, 256>>>(states);
    k_prep_awt<<<(H1d * Ad + 255) / 256, 256>>>(W1);
    k_prepW2<<<(H2d * H1d + 255) / 256, 256>>>(W2);
    k_gemmG<<<(Bd / 128) * (H1d / 128), 256>>>(states, W1, b1);
    k_main<<<(Bd * Ad) / 128, 256, SMEM_TOTAL>>>(b2, Wq, bq, out);
}

// round 5
// speedup vs baseline: 2.8208x; 1.0833x over previous
#include <cuda_runtime.h>
#include <cuda_bf16.h>

#define Bd   4096
#define Sd   512
#define Ad   64
#define H1d  1024
#define H2d  512
#define EPSf 1e-8f
#define TK   16

typedef unsigned long long ull;
typedef unsigned int u32;

// ------------------------- device scratch (no allocs allowed) --------------
__device__ float g_G[Bd * H1d];              // Gp[b][o] = G*invn[b] + b1[o]
__device__ float g_AWT[H1d * Ad];            // [o][a] layout
__device__ float g_invn[Bd];
__device__ __nv_bfloat16 g_W2hi[H2d * H1d];
__device__ __nv_bfloat16 g_W2lo[H2d * H1d];

// ------------------------- helpers -----------------------------------------
__device__ __forceinline__ u32 smem_u32(const void* p) {
    u32 a;
    asm("{ .reg .u64 t; cvta.to.shared.u64 t, %1; cvt.u32.u64 %0, t; }"
        : "=r"(a) : "l"(p));
    return a;
}
__device__ __forceinline__ ull pk2(float lo, float hi) {
    ull r;
    asm("mov.b64 %0, {%1, %2};" : "=l"(r)
        : "r"(__float_as_uint(lo)), "r"(__float_as_uint(hi)));
    return r;
}
__device__ __forceinline__ void upk2(ull v, float& lo, float& hi) {
    unsigned a, b;
    asm("mov.b64 {%0, %1}, %2;" : "=r"(a), "=r"(b) : "l"(v));
    lo = __uint_as_float(a); hi = __uint_as_float(b);
}
__device__ __forceinline__ ull ffma2(ull a, ull b, ull c) {
    ull d;
    asm("fma.rn.f32x2 %0, %1, %2, %3;" : "=l"(d) : "l"(a), "l"(b), "l"(c));
    return d;
}
// pack two f32 into bf16x2 (lo -> low 16 bits)
__device__ __forceinline__ u32 pkbf(float lo, float hi) {
    u32 r;
    asm("cvt.rn.bf16x2.f32 %0, %1, %2;" : "=r"(r) : "f"(hi), "f"(lo));
    return r;
}
__device__ __forceinline__ float bflo2f(u32 q) { return __uint_as_float(q << 16); }
__device__ __forceinline__ float bfhi2f(u32 q) { return __uint_as_float(q & 0xffff0000u); }

__device__ __forceinline__ void cpasync16(u32 dst, const void* src) {
    asm volatile("cp.async.cg.shared.global [%0], [%1], 16;"
                 :: "r"(dst), "l"(src) : "memory");
}
__device__ __forceinline__ void ldm4(u32* r, u32 addr) {
    asm volatile("ldmatrix.sync.aligned.m8n8.x4.shared.b16 {%0,%1,%2,%3}, [%4];"
                 : "=r"(r[0]), "=r"(r[1]), "=r"(r[2]), "=r"(r[3]) : "r"(addr));
}
__device__ __forceinline__ void mma16816(float* c, const u32* a, u32 b0, u32 b1) {
    asm volatile(
        "mma.sync.aligned.m16n8k16.row.col.f32.bf16.bf16.f32 "
        "{%0,%1,%2,%3}, {%4,%5,%6,%7}, {%8,%9}, {%0,%1,%2,%3};"
        : "+f"(c[0]), "+f"(c[1]), "+f"(c[2]), "+f"(c[3])
        : "r"(a[0]), "r"(a[1]), "r"(a[2]), "r"(a[3]), "r"(b0), "r"(b1));
}

// paired-row 64B tile addressing: logical (row, g) g=16B k-group 0..3
// two logical rows share one 128B line; XOR swizzle keeps ldmatrix/STS
// phases conflict-free (8 distinct bank-quads per 8 rows).
__device__ __forceinline__ u32 tile_off(int row, int g) {
    return (u32)((row >> 1) * 128 + (row & 1) * 64 +
                 ((g ^ ((row >> 1) & 3)) << 4));
}

// ---------------------------------------------------------------------------
// Prep kernels
// ---------------------------------------------------------------------------
__global__ void k_prep_awt(const float* __restrict__ W1) {
    int i = blockIdx.x * 256 + threadIdx.x;
    if (i < H1d * Ad) {
        int o = i >> 6, a = i & 63;
        g_AWT[i] = W1[o * 576 + 512 + a];
    }
}
__global__ void k_prepW2(const float* __restrict__ W2) {
    int i = blockIdx.x * 256 + threadIdx.x;
    if (i < H2d * H1d) {
        float v = W2[i];
        __nv_bfloat16 h = __float2bfloat16(v);
        g_W2hi[i] = h;
        g_W2lo[i] = __float2bfloat16(v - __bfloat162float(h));
    }
}
__global__ void k_invn(const float* __restrict__ states) {
    int w    = (blockIdx.x * blockDim.x + threadIdx.x) >> 5;
    int lane = threadIdx.x & 31;
    if (w >= Bd) return;
    const float* s = states + w * Sd;
    float acc = 0.f;
#pragma unroll 4
    for (int j = lane; j < Sd; j += 32) { float v = s[j]; acc += v * v; }
#pragma unroll
    for (int off = 16; off; off >>= 1) acc += __shfl_xor_sync(0xffffffffu, acc, off);
    if (lane == 0) g_invn[w] = 1.f / (sqrtf(acc + 1.f) + EPSf);
}

// ---------------------------------------------------------------------------
// Gp[b][o] = (states[b,:].W1[o,:512]) * invn[b] + b1[o]
// ---------------------------------------------------------------------------
__global__ void __launch_bounds__(256) k_gemmG(const float* __restrict__ states,
                                               const float* __restrict__ W1,
                                               const float* __restrict__ b1) {
    __shared__ __align__(16) float As[2][TK][128];
    __shared__ __align__(16) float Bs[2][TK][128];

    int b0  = (blockIdx.x >> 3) * 128;
    int o0  = (blockIdx.x & 7) * 128;
    int tid = threadIdx.x;
    int tm  = tid >> 4, tn = tid & 15;

    ull acc[4][8];
#pragma unroll
    for (int i = 0; i < 4; i++)
#pragma unroll
        for (int j = 0; j < 8; j++) acc[i][j] = 0ull;

    auto loadTile = [&](int c, int buf) {
        int k0 = c * TK;
#pragma unroll
        for (int it = 0; it < 2; it++) {
            int e = tid + it * 256;
            int r = e >> 2, kq = (e & 3) * 4;
            float4 va = *(const float4*)&states[(b0 + r) * Sd + k0 + kq];
            As[buf][kq + 0][r] = va.x; As[buf][kq + 1][r] = va.y;
            As[buf][kq + 2][r] = va.z; As[buf][kq + 3][r] = va.w;
            float4 vb = *(const float4*)&W1[(o0 + r) * 576 + k0 + kq];
            Bs[buf][kq + 0][r] = vb.x; Bs[buf][kq + 1][r] = vb.y;
            Bs[buf][kq + 2][r] = vb.z; Bs[buf][kq + 3][r] = vb.w;
        }
    };

    loadTile(0, 0);
    __syncthreads();
    const int NC = Sd / TK;
    for (int c = 0; c < NC; c++) {
        int buf = c & 1;
        if (c + 1 < NC) loadTile(c + 1, buf ^ 1);
#pragma unroll
        for (int kk = 0; kk < TK; kk++) {
            ull a2[4];
            const ull* ap = (const ull*)&As[buf][kk][tm * 8];
#pragma unroll
            for (int i = 0; i < 4; i++) a2[i] = ap[i];
            float4 bv0 = *(const float4*)&Bs[buf][kk][tn * 8];
            float4 bv1 = *(const float4*)&Bs[buf][kk][tn * 8 + 4];
            ull b2r[8];
            b2r[0] = pk2(bv0.x, bv0.x); b2r[1] = pk2(bv0.y, bv0.y);
            b2r[2] = pk2(bv0.z, bv0.z); b2r[3] = pk2(bv0.w, bv0.w);
            b2r[4] = pk2(bv1.x, bv1.x); b2r[5] = pk2(bv1.y, bv1.y);
            b2r[6] = pk2(bv1.z, bv1.z); b2r[7] = pk2(bv1.w, bv1.w);
#pragma unroll
            for (int i = 0; i < 4; i++)
#pragma unroll
                for (int j = 0; j < 8; j++)
                    acc[i][j] = ffma2(a2[i], b2r[j], acc[i][j]);
        }
        __syncthreads();
    }

    float4 b1a = *(const float4*)&b1[o0 + tn * 8];
    float4 b1b = *(const float4*)&b1[o0 + tn * 8 + 4];
    float bb[8] = {b1a.x, b1a.y, b1a.z, b1a.w, b1b.x, b1b.y, b1b.z, b1b.w};
#pragma unroll
    for (int i = 0; i < 4; i++) {
        int m0 = b0 + tm * 8 + i * 2;
        float inv0 = g_invn[m0], inv1 = g_invn[m0 + 1];
        float lo[8], hi[8];
#pragma unroll
        for (int j = 0; j < 8; j++) {
            upk2(acc[i][j], lo[j], hi[j]);
            lo[j] = fmaf(lo[j], inv0, bb[j]);
            hi[j] = fmaf(hi[j], inv1, bb[j]);
        }
        float* p0 = &g_G[(m0 + 0) * H1d + o0 + tn * 8];
        float* p1 = &g_G[(m0 + 1) * H1d + o0 + tn * 8];
        *(float4*)p0       = make_float4(lo[0], lo[1], lo[2], lo[3]);
        *(float4*)(p0 + 4) = make_float4(lo[4], lo[5], lo[6], lo[7]);
        *(float4*)p1       = make_float4(hi[0], hi[1], hi[2], hi[3]);
        *(float4*)(p1 + 4) = make_float4(hi[4], hi[5], hi[6], hi[7]);
    }
}

// ---------------------------------------------------------------------------
// Main fused kernel: one CTA = one batch row x 64 actions (M=64),
// full N=512 register-resident, K=1024 in 32 chunks of 32 (2-stage pipeline).
// A generated ONCE; epilogue (rinv, relu, Wq-dot) once at the end.
// ---------------------------------------------------------------------------
#define SOFF_GPS   0        // 1024 f32 (4 KB)
#define SOFF_B2    4096     // 512 f32
#define SOFF_WQ    6144     // 512 f32
#define SOFF_SS    8192     // 256 f32 (reused for q cross-warp partials)
#define SOFF_RINV  9216     // 64 f32
#define SOFF_STG   10240
#define AHI_OFF    0
#define ALO_OFF    4096
#define BHI_OFF    8192
#define BLO_OFF    40960
#define STG_BYTES  73728    // 4+4+32+32 KB
#define SMEM_TOTAL (SOFF_STG + 2 * STG_BYTES)   // 157696 B

#define KC 32               // K per chunk
#define NCHUNK (H1d / KC)   // 32

__global__ void __launch_bounds__(256, 1)
k_main(const float* __restrict__ b2, const float* __restrict__ Wq,
       const float* __restrict__ bq, float* __restrict__ out) {
    extern __shared__ __align__(1024) char smem[];
    u32 sb = smem_u32(smem);
    int tid = threadIdx.x;
    int wid = tid >> 5, lane = tid & 31;
    int warp_m = wid >> 2, warp_n = wid & 3;
    int bidx = blockIdx.x;                  // batch row
    int r0 = bidx * 64;

    float* Gps   = (float*)(smem + SOFF_GPS);
    float* b2s   = (float*)(smem + SOFF_B2);
    float* wqs   = (float*)(smem + SOFF_WQ);
    float* sss   = (float*)(smem + SOFF_SS);
    float* rinvs = (float*)(smem + SOFF_RINV);

    for (int i = tid; i < H1d; i += 256) Gps[i] = g_G[(size_t)bidx * H1d + i];
    for (int i = tid; i < H2d; i += 256) { b2s[i] = b2[i]; wqs[i] = Wq[i]; }
    __syncthreads();

    float inv = g_invn[bidx];
    // generator identity: m (=action) 0..63, kq = 16B k-group within chunk
    int gm = tid & 63, gkq = tid >> 6;

    float ss = 0.f;

    // A generator: h1 for chunk c (8 k-values) -> bf16 hi/lo
    auto genA = [&](int c, int buf) {
        char* stg = smem + SOFF_STG + buf * STG_BYTES;
        int o = c * KC + gkq * 8;
        const float* awt = g_AWT + (size_t)o * 64 + gm;
        float h[8];
#pragma unroll
        for (int j = 0; j < 8; j++)
            h[j] = fmaxf(fmaf(inv, awt[j * 64], Gps[o + j]), 0.f);
        float s2 = 0.f;
#pragma unroll
        for (int j = 0; j < 8; j++) s2 = fmaf(h[j], h[j], s2);
        ss += s2;
        u32 q0 = pkbf(h[0], h[1]), q1 = pkbf(h[2], h[3]);
        u32 q2 = pkbf(h[4], h[5]), q3 = pkbf(h[6], h[7]);
        u32 off = tile_off(gm, gkq);
        *(uint4*)(stg + AHI_OFF + off) = make_uint4(q0, q1, q2, q3);
        u32 l0 = pkbf(h[0] - bflo2f(q0), h[1] - bfhi2f(q0));
        u32 l1 = pkbf(h[2] - bflo2f(q1), h[3] - bfhi2f(q1));
        u32 l2 = pkbf(h[4] - bflo2f(q2), h[5] - bfhi2f(q2));
        u32 l3 = pkbf(h[6] - bflo2f(q3), h[7] - bfhi2f(q3));
        *(uint4*)(stg + ALO_OFF + off) = make_uint4(l0, l1, l2, l3);
    };

    // B loader: W2 hi/lo, 512 n-rows x 32 k (4 groups of 8)
    auto loadB = [&](int c, int buf) {
        u32 bh = sb + SOFF_STG + buf * STG_BYTES + BHI_OFF;
        u32 bl = bh + (BLO_OFF - BHI_OFF);
        const __nv_bfloat16* w2h = g_W2hi + c * KC;
        const __nv_bfloat16* w2l = g_W2lo + c * KC;
#pragma unroll
        for (int i = 0; i < 8; i++) {
            int e = tid + i * 256;
            int n = e >> 2, g = e & 3;
            cpasync16(bh + tile_off(n, g), w2h + (size_t)n * H1d + g * 8);
        }
#pragma unroll
        for (int i = 0; i < 8; i++) {
            int e = tid + i * 256;
            int n = e >> 2, g = e & 3;
            cpasync16(bl + tile_off(n, g), w2l + (size_t)n * H1d + g * 8);
        }
        asm volatile("cp.async.commit_group;" ::: "memory");
    };

    int lt = lane & 15, lh = lane >> 4;

    float acc[2][16][4];
#pragma unroll
    for (int i = 0; i < 2; i++)
#pragma unroll
        for (int j = 0; j < 16; j++)
#pragma unroll
            for (int k = 0; k < 4; k++) acc[i][j][k] = 0.f;

    genA(0, 0);
    loadB(0, 0);
    asm volatile("cp.async.wait_group 0;" ::: "memory");
    __syncthreads();

    for (int c = 0; c < NCHUNK; c++) {
        int buf = c & 1;
        if (c + 1 < NCHUNK) { genA(c + 1, buf ^ 1); loadB(c + 1, buf ^ 1); }

        u32 abase = sb + SOFF_STG + buf * STG_BYTES;
#pragma unroll
        for (int ks = 0; ks < 2; ks++) {
            int g = ks * 2 + lh;
            // A fragments (hi+lo) for this warp's 32 rows
            u32 ah[2][4], al[2][4];
#pragma unroll
            for (int mt = 0; mt < 2; mt++) {
                int row = warp_m * 32 + mt * 16 + lt;
                u32 off = tile_off(row, g);
                ldm4(ah[mt], abase + AHI_OFF + off);
                ldm4(al[mt], abase + ALO_OFF + off);
            }
            // 8 pairs of n8-tiles across this warp's 128 n-columns
#pragma unroll
            for (int nb = 0; nb < 8; nb++) {
                int nrow = warp_n * 128 + nb * 16 + lt;
                u32 off = tile_off(nrow, g);
                u32 bh[4], bl[4];
                ldm4(bh, abase + BHI_OFF + off);
                ldm4(bl, abase + BLO_OFF + off);
#pragma unroll
                for (int mt = 0; mt < 2; mt++)
#pragma unroll
                    for (int s = 0; s < 2; s++) {
                        float* cc = acc[mt][nb * 2 + s];
                        mma16816(cc, ah[mt], bh[s], bh[s + 2]);
                        mma16816(cc, ah[mt], bl[s], bl[s + 2]);
                        mma16816(cc, al[mt], bh[s], bh[s + 2]);
                    }
            }
        }
        asm volatile("cp.async.wait_group 0;" ::: "memory");
        __syncthreads();
    }

    // ---- rinv: reduce ss over the 4 k-slices of each m-row ----
    sss[tid] = ss;
    __syncthreads();
    if (tid < 64)
        rinvs[tid] = 1.f / (sqrtf(sss[tid] + sss[64 + tid] +
                                  sss[128 + tid] + sss[192 + tid]) + EPSf);
    __syncthreads();

    // ---- epilogue: q[m] = sum_n relu(acc*rinv + b2) * Wq ----
    float qacc[4] = {0.f, 0.f, 0.f, 0.f};
#pragma unroll
    for (int mt = 0; mt < 2; mt++) {
        int rlo = warp_m * 32 + mt * 16 + (lane >> 2);
        float rv0 = rinvs[rlo], rv1 = rinvs[rlo + 8];
#pragma unroll
        for (int nt = 0; nt < 16; nt++) {
            int n = warp_n * 128 + nt * 8 + (lane & 3) * 2;
            float bb0 = b2s[n], bb1 = b2s[n + 1];
            float w0 = wqs[n], w1 = wqs[n + 1];
            const float* cc = acc[mt][nt];
            qacc[mt * 2 + 0] += fmaxf(fmaf(cc[0], rv0, bb0), 0.f) * w0 +
                                fmaxf(fmaf(cc[1], rv0, bb1), 0.f) * w1;
            qacc[mt * 2 + 1] += fmaxf(fmaf(cc[2], rv1, bb0), 0.f) * w0 +
                                fmaxf(fmaf(cc[3], rv1, bb1), 0.f) * w1;
        }
    }
#pragma unroll
    for (int off = 1; off <= 2; off <<= 1)
#pragma unroll
        for (int i = 0; i < 4; i++)
            qacc[i] += __shfl_xor_sync(0xffffffffu, qacc[i], off);

    __syncthreads();          // sss region reuse for q partials
    if ((lane & 3) == 0) {
#pragma unroll
        for (int mt = 0; mt < 2; mt++)
#pragma unroll
            for (int hh = 0; hh < 2; hh++) {
                int row = warp_m * 32 + mt * 16 + hh * 8 + (lane >> 2);
                sss[row * 4 + warp_n] = qacc[mt * 2 + hh];
            }
    }
    __syncthreads();
    if (tid < 64)
        out[r0 + tid] = sss[tid * 4] + sss[tid * 4 + 1] +
                        sss[tid * 4 + 2] + sss[tid * 4 + 3] + __ldg(bq);
}

// ---------------------------------------------------------------------------
extern "C" void kernel_launch(void* const* d_in, const int* in_sizes, int n_in,
                              void* d_out, int out_size) {
    const float* states = (const float*)d_in[0];
    const float* W1     = (const float*)d_in[1];
    const float* b1     = (const float*)d_in[2];
    const float* W2     = (const float*)d_in[3];
    const float* b2     = (const float*)d_in[4];
    const float* Wq     = (const float*)d_in[5];
    const float* bq     = (const float*)d_in[6];
    float* out = (float*)d_out;

    cudaFuncSetAttribute((const void*)k_main,
                         cudaFuncAttributeMaxDynamicSharedMemorySize, SMEM_TOTAL);

    k_invn<<<Bd / 8, 256>>>(states);
    k_prep_awt<<<(H1d * Ad + 255) / 256, 256>>>(W1);
    k_prepW2<<<(H2d * H1d + 255) / 256, 256>>>(W2);
    k_gemmG<<<(Bd / 128) * (H1d / 128), 256>>>(states, W1, b1);
    k_main<<<Bd, 256, SMEM_TOTAL>>>(b2, Wq, bq, out);
}

// round 6
// speedup vs baseline: 3.0998x; 1.0989x over previous
#include <cuda_runtime.h>
#include <cuda_bf16.h>

#define Bd   4096
#define Sd   512
#define Ad   64
#define H1d  1024
#define H2d  512
#define EPSf 1e-8f
#define TK   16

typedef unsigned long long ull;
typedef unsigned int u32;

// ------------------------- device scratch (no allocs allowed) --------------
__device__ float g_G[Bd * H1d];              // Gp[b][o] = G*invn[b] + b1[o]
__device__ float g_AWT[H1d * Ad];            // [o][a] layout
__device__ float g_invn[Bd];
__device__ __nv_bfloat16 g_W2hi[H2d * H1d];
__device__ __nv_bfloat16 g_W2lo[H2d * H1d];

// ------------------------- helpers -----------------------------------------
__device__ __forceinline__ u32 smem_u32(const void* p) {
    u32 a;
    asm("{ .reg .u64 t; cvta.to.shared.u64 t, %1; cvt.u32.u64 %0, t; }"
        : "=r"(a) : "l"(p));
    return a;
}
__device__ __forceinline__ ull pk2(float lo, float hi) {
    ull r;
    asm("mov.b64 %0, {%1, %2};" : "=l"(r)
        : "r"(__float_as_uint(lo)), "r"(__float_as_uint(hi)));
    return r;
}
__device__ __forceinline__ void upk2(ull v, float& lo, float& hi) {
    unsigned a, b;
    asm("mov.b64 {%0, %1}, %2;" : "=r"(a), "=r"(b) : "l"(v));
    lo = __uint_as_float(a); hi = __uint_as_float(b);
}
__device__ __forceinline__ ull ffma2(ull a, ull b, ull c) {
    ull d;
    asm("fma.rn.f32x2 %0, %1, %2, %3;" : "=l"(d) : "l"(a), "l"(b), "l"(c));
    return d;
}
// pack two f32 into bf16x2 (lo -> low 16 bits)
__device__ __forceinline__ u32 pkbf(float lo, float hi) {
    u32 r;
    asm("cvt.rn.bf16x2.f32 %0, %1, %2;" : "=r"(r) : "f"(hi), "f"(lo));
    return r;
}
__device__ __forceinline__ float bflo2f(u32 q) { return __uint_as_float(q << 16); }
__device__ __forceinline__ float bfhi2f(u32 q) { return __uint_as_float(q & 0xffff0000u); }

__device__ __forceinline__ void cpasync16(u32 dst, const void* src) {
    asm volatile("cp.async.cg.shared.global [%0], [%1], 16;"
                 :: "r"(dst), "l"(src) : "memory");
}
__device__ __forceinline__ void ldm4(u32* r, u32 addr) {
    asm volatile("ldmatrix.sync.aligned.m8n8.x4.shared.b16 {%0,%1,%2,%3}, [%4];"
                 : "=r"(r[0]), "=r"(r[1]), "=r"(r[2]), "=r"(r[3]) : "r"(addr));
}
__device__ __forceinline__ void mma16816(float* c, const u32* a, u32 b0, u32 b1) {
    asm volatile(
        "mma.sync.aligned.m16n8k16.row.col.f32.bf16.bf16.f32 "
        "{%0,%1,%2,%3}, {%4,%5,%6,%7}, {%8,%9}, {%0,%1,%2,%3};"
        : "+f"(c[0]), "+f"(c[1]), "+f"(c[2]), "+f"(c[3])
        : "r"(a[0]), "r"(a[1]), "r"(a[2]), "r"(a[3]), "r"(b0), "r"(b1));
}

// 128B-row SW128 tile addressing: row has 8 16B k-groups
__device__ __forceinline__ u32 toff(int row, int g) {
    return (u32)(row * 128 + ((g ^ (row & 7)) << 4));
}

// ---------------------------------------------------------------------------
// Prep (merged): AWT gather + W2 bf16 hi/lo split
// ---------------------------------------------------------------------------
__global__ void k_prep(const float* __restrict__ W1,
                       const float* __restrict__ W2) {
    int i = blockIdx.x * 256 + threadIdx.x;
    if (i < H1d * Ad) {
        int o = i >> 6, a = i & 63;
        g_AWT[i] = W1[o * 576 + 512 + a];
    }
    int j = i - H1d * Ad;
    if (j >= 0 && j < H2d * H1d) {
        float v = W2[j];
        __nv_bfloat16 h = __float2bfloat16(v);
        g_W2hi[j] = h;
        g_W2lo[j] = __float2bfloat16(v - __bfloat162float(h));
    }
}
__global__ void k_invn(const float* __restrict__ states) {
    int w    = (blockIdx.x * blockDim.x + threadIdx.x) >> 5;
    int lane = threadIdx.x & 31;
    if (w >= Bd) return;
    const float* s = states + w * Sd;
    float acc = 0.f;
#pragma unroll 4
    for (int j = lane; j < Sd; j += 32) { float v = s[j]; acc += v * v; }
#pragma unroll
    for (int off = 16; off; off >>= 1) acc += __shfl_xor_sync(0xffffffffu, acc, off);
    if (lane == 0) g_invn[w] = 1.f / (sqrtf(acc + 1.f) + EPSf);
}

// ---------------------------------------------------------------------------
// Gp[b][o] = (states[b,:].W1[o,:512]) * invn[b] + b1[o]
// ---------------------------------------------------------------------------
__global__ void __launch_bounds__(256) k_gemmG(const float* __restrict__ states,
                                               const float* __restrict__ W1,
                                               const float* __restrict__ b1) {
    __shared__ __align__(16) float As[2][TK][128];
    __shared__ __align__(16) float Bs[2][TK][128];

    int b0  = (blockIdx.x >> 3) * 128;
    int o0  = (blockIdx.x & 7) * 128;
    int tid = threadIdx.x;
    int tm  = tid >> 4, tn = tid & 15;

    ull acc[4][8];
#pragma unroll
    for (int i = 0; i < 4; i++)
#pragma unroll
        for (int j = 0; j < 8; j++) acc[i][j] = 0ull;

    auto loadTile = [&](int c, int buf) {
        int k0 = c * TK;
#pragma unroll
        for (int it = 0; it < 2; it++) {
            int e = tid + it * 256;
            int r = e >> 2, kq = (e & 3) * 4;
            float4 va = *(const float4*)&states[(b0 + r) * Sd + k0 + kq];
            As[buf][kq + 0][r] = va.x; As[buf][kq + 1][r] = va.y;
            As[buf][kq + 2][r] = va.z; As[buf][kq + 3][r] = va.w;
            float4 vb = *(const float4*)&W1[(o0 + r) * 576 + k0 + kq];
            Bs[buf][kq + 0][r] = vb.x; Bs[buf][kq + 1][r] = vb.y;
            Bs[buf][kq + 2][r] = vb.z; Bs[buf][kq + 3][r] = vb.w;
        }
    };

    loadTile(0, 0);
    __syncthreads();
    const int NC = Sd / TK;
    for (int c = 0; c < NC; c++) {
        int buf = c & 1;
        if (c + 1 < NC) loadTile(c + 1, buf ^ 1);
#pragma unroll
        for (int kk = 0; kk < TK; kk++) {
            ull a2[4];
            const ull* ap = (const ull*)&As[buf][kk][tm * 8];
#pragma unroll
            for (int i = 0; i < 4; i++) a2[i] = ap[i];
            float4 bv0 = *(const float4*)&Bs[buf][kk][tn * 8];
            float4 bv1 = *(const float4*)&Bs[buf][kk][tn * 8 + 4];
            ull b2r[8];
            b2r[0] = pk2(bv0.x, bv0.x); b2r[1] = pk2(bv0.y, bv0.y);
            b2r[2] = pk2(bv0.z, bv0.z); b2r[3] = pk2(bv0.w, bv0.w);
            b2r[4] = pk2(bv1.x, bv1.x); b2r[5] = pk2(bv1.y, bv1.y);
            b2r[6] = pk2(bv1.z, bv1.z); b2r[7] = pk2(bv1.w, bv1.w);
#pragma unroll
            for (int i = 0; i < 4; i++)
#pragma unroll
                for (int j = 0; j < 8; j++)
                    acc[i][j] = ffma2(a2[i], b2r[j], acc[i][j]);
        }
        __syncthreads();
    }

    float4 b1a = *(const float4*)&b1[o0 + tn * 8];
    float4 b1b = *(const float4*)&b1[o0 + tn * 8 + 4];
    float bb[8] = {b1a.x, b1a.y, b1a.z, b1a.w, b1b.x, b1b.y, b1b.z, b1b.w};
#pragma unroll
    for (int i = 0; i < 4; i++) {
        int m0 = b0 + tm * 8 + i * 2;
        float inv0 = g_invn[m0], inv1 = g_invn[m0 + 1];
        float lo[8], hi[8];
#pragma unroll
        for (int j = 0; j < 8; j++) {
            upk2(acc[i][j], lo[j], hi[j]);
            lo[j] = fmaf(lo[j], inv0, bb[j]);
            hi[j] = fmaf(hi[j], inv1, bb[j]);
        }
        float* p0 = &g_G[(m0 + 0) * H1d + o0 + tn * 8];
        float* p1 = &g_G[(m0 + 1) * H1d + o0 + tn * 8];
        *(float4*)p0       = make_float4(lo[0], lo[1], lo[2], lo[3]);
        *(float4*)(p0 + 4) = make_float4(lo[4], lo[5], lo[6], lo[7]);
        *(float4*)p1       = make_float4(hi[0], hi[1], hi[2], hi[3]);
        *(float4*)(p1 + 4) = make_float4(hi[4], hi[5], hi[6], hi[7]);
    }
}

// ---------------------------------------------------------------------------
// Main fused kernel: M=128 rows/CTA (2 batch x 64 actions), N=512 in
// 2 passes of 256, K=1024 in 16 chunks of 64 (2-stage pipeline).
// ---------------------------------------------------------------------------
#define SOFF_GPS   0        // 2*1024 f32 (8 KB)
#define SOFF_B2    8192     // 512 f32
#define SOFF_WQ    10240    // 512 f32
#define SOFF_SS    12288    // 512 f32 (ss: 256 used; q partials: 512 used)
#define SOFF_RINV  14336    // 128 f32
#define SOFF_INVN  14848    // 2 f32
#define SOFF_STG   15360
#define AHI_OFF    0        // 128 rows x 128B = 16 KB
#define ALO_OFF    16384
#define BHI_OFF    32768    // 256 rows x 128B = 32 KB
#define BLO_OFF    65536
#define STG_BYTES  98304    // 96 KB per stage
#define SMEM_TOTAL (SOFF_STG + 2 * STG_BYTES)   // 211968 B

#define KC  64
#define NCH (H1d / KC)      // 16 chunks per pass

__global__ void __launch_bounds__(256, 1)
k_main(const float* __restrict__ b2, const float* __restrict__ Wq,
       const float* __restrict__ bq, float* __restrict__ out) {
    extern __shared__ __align__(1024) char smem[];
    u32 sb = smem_u32(smem);
    int tid = threadIdx.x;
    int wid = tid >> 5, lane = tid & 31;
    int warp_m = wid >> 2, warp_n = wid & 3;       // 2 x 4 warp grid
    int r0 = blockIdx.x * 128, b0 = r0 >> 6;       // 2 batch rows

    float* Gps   = (float*)(smem + SOFF_GPS);
    float* b2s   = (float*)(smem + SOFF_B2);
    float* wqs   = (float*)(smem + SOFF_WQ);
    float* sss   = (float*)(smem + SOFF_SS);
    float* rinvs = (float*)(smem + SOFF_RINV);
    float* invns = (float*)(smem + SOFF_INVN);

    for (int i = tid; i < 2 * H1d; i += 256)
        Gps[i] = g_G[(size_t)(b0 + (i >> 10)) * H1d + (i & 1023)];
    for (int i = tid; i < H2d; i += 256) { b2s[i] = b2[i]; wqs[i] = Wq[i]; }
    if (tid < 2) invns[tid] = g_invn[b0 + tid];
    __syncthreads();

    // generator identity: row gm (0..127), k-half gh (0/1)
    int gm = tid & 127, gh = tid >> 7;
    int ga = gm & 63, gbl = gm >> 6;
    float inv = invns[gbl];
    const float* gpr = Gps + gbl * H1d;
    float ss = 0.f;

    // A generator: chunk c (64 k), this thread does 32 k (4 groups of 8)
    auto genA = [&](int c, int buf, bool do_ss) {
        char* stg = smem + SOFF_STG + buf * STG_BYTES;
        int ob = c * KC + gh * 32;
#pragma unroll
        for (int j4 = 0; j4 < 4; j4++) {
            int o = ob + j4 * 8;
            const float* awt = g_AWT + (size_t)o * 64 + ga;
            float h[8];
#pragma unroll
            for (int j = 0; j < 8; j++)
                h[j] = fmaxf(fmaf(inv, awt[j * 64], gpr[o + j]), 0.f);
            if (do_ss) {
                float s2 = 0.f;
#pragma unroll
                for (int j = 0; j < 8; j++) s2 = fmaf(h[j], h[j], s2);
                ss += s2;
            }
            u32 q0 = pkbf(h[0], h[1]), q1 = pkbf(h[2], h[3]);
            u32 q2 = pkbf(h[4], h[5]), q3 = pkbf(h[6], h[7]);
            u32 off = toff(gm, gh * 4 + j4);
            *(uint4*)(stg + AHI_OFF + off) = make_uint4(q0, q1, q2, q3);
            u32 l0 = pkbf(h[0] - bflo2f(q0), h[1] - bfhi2f(q0));
            u32 l1 = pkbf(h[2] - bflo2f(q1), h[3] - bfhi2f(q1));
            u32 l2 = pkbf(h[4] - bflo2f(q2), h[5] - bfhi2f(q2));
            u32 l3 = pkbf(h[6] - bflo2f(q3), h[7] - bfhi2f(q3));
            *(uint4*)(stg + ALO_OFF + off) = make_uint4(l0, l1, l2, l3);
        }
    };

    // B loader: W2 hi/lo, 256 n-rows x 64 k per chunk
    auto loadB = [&](int pass, int c, int buf) {
        u32 bh = sb + SOFF_STG + buf * STG_BYTES + BHI_OFF;
        u32 bl = bh + (BLO_OFF - BHI_OFF);
        const __nv_bfloat16* w2h = g_W2hi + (size_t)(pass * 256) * H1d + c * KC;
        const __nv_bfloat16* w2l = g_W2lo + (size_t)(pass * 256) * H1d + c * KC;
#pragma unroll
        for (int i = 0; i < 8; i++) {
            int e = tid + i * 256;
            int n = e >> 3, g = e & 7;
            cpasync16(bh + toff(n, g), w2h + (size_t)n * H1d + g * 8);
        }
#pragma unroll
        for (int i = 0; i < 8; i++) {
            int e = tid + i * 256;
            int n = e >> 3, g = e & 7;
            cpasync16(bl + toff(n, g), w2l + (size_t)n * H1d + g * 8);
        }
        asm volatile("cp.async.commit_group;" ::: "memory");
    };

    int lt = lane & 15, lh = lane >> 4;
    float qacc[8];
#pragma unroll
    for (int i = 0; i < 8; i++) qacc[i] = 0.f;

    for (int pass = 0; pass < 2; pass++) {
        float acc[4][8][4];
#pragma unroll
        for (int i = 0; i < 4; i++)
#pragma unroll
            for (int j = 0; j < 8; j++)
#pragma unroll
                for (int k = 0; k < 4; k++) acc[i][j][k] = 0.f;

        genA(0, 0, pass == 0);
        loadB(pass, 0, 0);
        asm volatile("cp.async.wait_group 0;" ::: "memory");
        __syncthreads();

        for (int c = 0; c < NCH; c++) {
            int buf = c & 1;
            if (c + 1 < NCH) {
                genA(c + 1, buf ^ 1, pass == 0);
                loadB(pass, c + 1, buf ^ 1);
            }
            u32 abase = sb + SOFF_STG + buf * STG_BYTES;
#pragma unroll
            for (int ks = 0; ks < 4; ks++) {
                int g = ks * 2 + lh;
                u32 ah[4][4], al[4][4];
#pragma unroll
                for (int mt = 0; mt < 4; mt++) {
                    int row = warp_m * 64 + mt * 16 + lt;
                    u32 off = toff(row, g);
                    ldm4(ah[mt], abase + AHI_OFF + off);
                    ldm4(al[mt], abase + ALO_OFF + off);
                }
#pragma unroll
                for (int nb = 0; nb < 4; nb++) {
                    int nrow = warp_n * 64 + nb * 16 + lt;
                    u32 off = toff(nrow, g);
                    u32 bh[4], bl[4];
                    ldm4(bh, abase + BHI_OFF + off);
                    ldm4(bl, abase + BLO_OFF + off);
#pragma unroll
                    for (int mt = 0; mt < 4; mt++)
#pragma unroll
                        for (int s = 0; s < 2; s++) {
                            float* cc = acc[mt][nb * 2 + s];
                            mma16816(cc, ah[mt], bh[s], bh[s + 2]);
                            mma16816(cc, ah[mt], bl[s], bl[s + 2]);
                            mma16816(cc, al[mt], bh[s], bh[s + 2]);
                        }
                }
            }
            asm volatile("cp.async.wait_group 0;" ::: "memory");
            __syncthreads();
        }

        if (pass == 0) {
            // rinv: 2 threads per row contributed half of K each
            sss[tid] = ss;
            __syncthreads();
            if (tid < 128)
                rinvs[tid] = 1.f / (sqrtf(sss[tid] + sss[tid + 128]) + EPSf);
            __syncthreads();
        }

        // epilogue: q += relu(acc * rinv + b2) * Wq for this pass's 256 n
#pragma unroll
        for (int mt = 0; mt < 4; mt++) {
            int rlo = warp_m * 64 + mt * 16 + (lane >> 2);
            float rv0 = rinvs[rlo], rv1 = rinvs[rlo + 8];
#pragma unroll
            for (int nt = 0; nt < 8; nt++) {
                int n = pass * 256 + warp_n * 64 + nt * 8 + (lane & 3) * 2;
                float bb0 = b2s[n], bb1 = b2s[n + 1];
                float w0 = wqs[n], w1 = wqs[n + 1];
                const float* cc = acc[mt][nt];
                qacc[mt * 2 + 0] += fmaxf(fmaf(cc[0], rv0, bb0), 0.f) * w0 +
                                    fmaxf(fmaf(cc[1], rv0, bb1), 0.f) * w1;
                qacc[mt * 2 + 1] += fmaxf(fmaf(cc[2], rv1, bb0), 0.f) * w0 +
                                    fmaxf(fmaf(cc[3], rv1, bb1), 0.f) * w1;
            }
        }
    }

    // reduce q over the 4 lanes of each quad
#pragma unroll
    for (int off = 1; off <= 2; off <<= 1)
#pragma unroll
        for (int i = 0; i < 8; i++)
            qacc[i] += __shfl_xor_sync(0xffffffffu, qacc[i], off);

    __syncthreads();          // reuse sss for q cross-warp partials (512 f32)
    if ((lane & 3) == 0) {
#pragma unroll
        for (int mt = 0; mt < 4; mt++)
#pragma unroll
            for (int hh = 0; hh < 2; hh++) {
                int row = warp_m * 64 + mt * 16 + hh * 8 + (lane >> 2);
                sss[row * 4 + warp_n] = qacc[mt * 2 + hh];
            }
    }
    __syncthreads();
    if (tid < 128)
        out[r0 + tid] = sss[tid * 4] + sss[tid * 4 + 1] +
                        sss[tid * 4 + 2] + sss[tid * 4 + 3] + __ldg(bq);
}

// ---------------------------------------------------------------------------
extern "C" void kernel_launch(void* const* d_in, const int* in_sizes, int n_in,
                              void* d_out, int out_size) {
    const float* states = (const float*)d_in[0];
    const float* W1     = (const float*)d_in[1];
    const float* b1     = (const float*)d_in[2];
    const float* W2     = (const float*)d_in[3];
    const float* b2     = (const float*)d_in[4];
    const float* Wq     = (const float*)d_in[5];
    const float* bq     = (const float*)d_in[6];
    float* out = (float*)d_out;

    cudaFuncSetAttribute((const void*)k_main,
                         cudaFuncAttributeMaxDynamicSharedMemorySize, SMEM_TOTAL);

    k_invn<<<Bd / 8, 256>>>(states);
    k_prep<<<(H1d * Ad + H2d * H1d + 255) / 256, 256>>>(W1, W2);
    k_gemmG<<<(Bd / 128) * (H1d / 128), 256>>>(states, W1, b1);
    k_main<<<(Bd * Ad) / 128, 256, SMEM_TOTAL>>>(b2, Wq, bq, out);
}

// round 7
// speedup vs baseline: 4.3292x; 1.3966x over previous
#include <cuda_runtime.h>
#include <cuda_bf16.h>
#include <cuda_fp16.h>

#define Bd   4096
#define Sd   512
#define Ad   64
#define H1d  1024
#define H2d  512
#define EPSf 1e-8f
#define TK   16

typedef unsigned long long ull;
typedef unsigned int u32;

// ------------------------- device scratch (no allocs allowed) --------------
__device__ float g_G[Bd * H1d];              // Gp[b][o] = G*invn[b] + b1[o]
__device__ float g_AWT[H1d * Ad];            // [o][a] layout
__device__ float g_invn[Bd];
__device__ __half g_W2h[H2d * H1d];          // fp16(W2)

// ------------------------- helpers -----------------------------------------
__device__ __forceinline__ u32 smem_u32(const void* p) {
    u32 a;
    asm("{ .reg .u64 t; cvta.to.shared.u64 t, %1; cvt.u32.u64 %0, t; }"
        : "=r"(a) : "l"(p));
    return a;
}
__device__ __forceinline__ ull pk2(float lo, float hi) {
    ull r;
    asm("mov.b64 %0, {%1, %2};" : "=l"(r)
        : "r"(__float_as_uint(lo)), "r"(__float_as_uint(hi)));
    return r;
}
__device__ __forceinline__ void upk2(ull v, float& lo, float& hi) {
    unsigned a, b;
    asm("mov.b64 {%0, %1}, %2;" : "=r"(a), "=r"(b) : "l"(v));
    lo = __uint_as_float(a); hi = __uint_as_float(b);
}
__device__ __forceinline__ ull ffma2(ull a, ull b, ull c) {
    ull d;
    asm("fma.rn.f32x2 %0, %1, %2, %3;" : "=l"(d) : "l"(a), "l"(b), "l"(c));
    return d;
}
// pack two f32 into f16x2 (lo -> low 16 bits)
__device__ __forceinline__ u32 pkhf(float lo, float hi) {
    u32 r;
    asm("cvt.rn.f16x2.f32 %0, %1, %2;" : "=r"(r) : "f"(hi), "f"(lo));
    return r;
}
__device__ __forceinline__ float hlo2f(u32 q) {
    __half2 v = *reinterpret_cast<__half2*>(&q);
    return __low2float(v);
}
__device__ __forceinline__ float hhi2f(u32 q) {
    __half2 v = *reinterpret_cast<__half2*>(&q);
    return __high2float(v);
}

__device__ __forceinline__ void cpasync16(u32 dst, const void* src) {
    asm volatile("cp.async.cg.shared.global [%0], [%1], 16;"
                 :: "r"(dst), "l"(src) : "memory");
}
__device__ __forceinline__ void ldm4(u32* r, u32 addr) {
    asm volatile("ldmatrix.sync.aligned.m8n8.x4.shared.b16 {%0,%1,%2,%3}, [%4];"
                 : "=r"(r[0]), "=r"(r[1]), "=r"(r[2]), "=r"(r[3]) : "r"(addr));
}
__device__ __forceinline__ void mma16816(float* c, const u32* a, u32 b0, u32 b1) {
    asm volatile(
        "mma.sync.aligned.m16n8k16.row.col.f32.f16.f16.f32 "
        "{%0,%1,%2,%3}, {%4,%5,%6,%7}, {%8,%9}, {%0,%1,%2,%3};"
        : "+f"(c[0]), "+f"(c[1]), "+f"(c[2]), "+f"(c[3])
        : "r"(a[0]), "r"(a[1]), "r"(a[2]), "r"(a[3]), "r"(b0), "r"(b1));
}

// 128B-row SW128 tile addressing: row has 8 16B k-groups
__device__ __forceinline__ u32 toff(int row, int g) {
    return (u32)(row * 128 + ((g ^ (row & 7)) << 4));
}

// ---------------------------------------------------------------------------
// Prep (merged): AWT gather + W2 fp16 convert
// ---------------------------------------------------------------------------
__global__ void k_prep(const float* __restrict__ W1,
                       const float* __restrict__ W2) {
    int i = blockIdx.x * 256 + threadIdx.x;
    if (i < H1d * Ad) {
        int o = i >> 6, a = i & 63;
        g_AWT[i] = W1[o * 576 + 512 + a];
    }
    int j = i - H1d * Ad;
    if (j >= 0 && j < H2d * H1d) {
        g_W2h[j] = __float2half_rn(W2[j]);
    }
}
__global__ void k_invn(const float* __restrict__ states) {
    int w    = (blockIdx.x * blockDim.x + threadIdx.x) >> 5;
    int lane = threadIdx.x & 31;
    if (w >= Bd) return;
    const float* s = states + w * Sd;
    float acc = 0.f;
#pragma unroll 4
    for (int j = lane; j < Sd; j += 32) { float v = s[j]; acc += v * v; }
#pragma unroll
    for (int off = 16; off; off >>= 1) acc += __shfl_xor_sync(0xffffffffu, acc, off);
    if (lane == 0) g_invn[w] = 1.f / (sqrtf(acc + 1.f) + EPSf);
}

// ---------------------------------------------------------------------------
// Gp[b][o] = (states[b,:].W1[o,:512]) * invn[b] + b1[o]   (fp32 SIMT)
// ---------------------------------------------------------------------------
__global__ void __launch_bounds__(256) k_gemmG(const float* __restrict__ states,
                                               const float* __restrict__ W1,
                                               const float* __restrict__ b1) {
    __shared__ __align__(16) float As[2][TK][128];
    __shared__ __align__(16) float Bs[2][TK][128];

    int b0  = (blockIdx.x >> 3) * 128;
    int o0  = (blockIdx.x & 7) * 128;
    int tid = threadIdx.x;
    int tm  = tid >> 4, tn = tid & 15;

    ull acc[4][8];
#pragma unroll
    for (int i = 0; i < 4; i++)
#pragma unroll
        for (int j = 0; j < 8; j++) acc[i][j] = 0ull;

    auto loadTile = [&](int c, int buf) {
        int k0 = c * TK;
#pragma unroll
        for (int it = 0; it < 2; it++) {
            int e = tid + it * 256;
            int r = e >> 2, kq = (e & 3) * 4;
            float4 va = *(const float4*)&states[(b0 + r) * Sd + k0 + kq];
            As[buf][kq + 0][r] = va.x; As[buf][kq + 1][r] = va.y;
            As[buf][kq + 2][r] = va.z; As[buf][kq + 3][r] = va.w;
            float4 vb = *(const float4*)&W1[(o0 + r) * 576 + k0 + kq];
            Bs[buf][kq + 0][r] = vb.x; Bs[buf][kq + 1][r] = vb.y;
            Bs[buf][kq + 2][r] = vb.z; Bs[buf][kq + 3][r] = vb.w;
        }
    };

    loadTile(0, 0);
    __syncthreads();
    const int NC = Sd / TK;
    for (int c = 0; c < NC; c++) {
        int buf = c & 1;
        if (c + 1 < NC) loadTile(c + 1, buf ^ 1);
#pragma unroll
        for (int kk = 0; kk < TK; kk++) {
            ull a2[4];
            const ull* ap = (const ull*)&As[buf][kk][tm * 8];
#pragma unroll
            for (int i = 0; i < 4; i++) a2[i] = ap[i];
            float4 bv0 = *(const float4*)&Bs[buf][kk][tn * 8];
            float4 bv1 = *(const float4*)&Bs[buf][kk][tn * 8 + 4];
            ull b2r[8];
            b2r[0] = pk2(bv0.x, bv0.x); b2r[1] = pk2(bv0.y, bv0.y);
            b2r[2] = pk2(bv0.z, bv0.z); b2r[3] = pk2(bv0.w, bv0.w);
            b2r[4] = pk2(bv1.x, bv1.x); b2r[5] = pk2(bv1.y, bv1.y);
            b2r[6] = pk2(bv1.z, bv1.z); b2r[7] = pk2(bv1.w, bv1.w);
#pragma unroll
            for (int i = 0; i < 4; i++)
#pragma unroll
                for (int j = 0; j < 8; j++)
                    acc[i][j] = ffma2(a2[i], b2r[j], acc[i][j]);
        }
        __syncthreads();
    }

    float4 b1a = *(const float4*)&b1[o0 + tn * 8];
    float4 b1b = *(const float4*)&b1[o0 + tn * 8 + 4];
    float bb[8] = {b1a.x, b1a.y, b1a.z, b1a.w, b1b.x, b1b.y, b1b.z, b1b.w};
#pragma unroll
    for (int i = 0; i < 4; i++) {
        int m0 = b0 + tm * 8 + i * 2;
        float inv0 = g_invn[m0], inv1 = g_invn[m0 + 1];
        float lo[8], hi[8];
#pragma unroll
        for (int j = 0; j < 8; j++) {
            upk2(acc[i][j], lo[j], hi[j]);
            lo[j] = fmaf(lo[j], inv0, bb[j]);
            hi[j] = fmaf(hi[j], inv1, bb[j]);
        }
        float* p0 = &g_G[(m0 + 0) * H1d + o0 + tn * 8];
        float* p1 = &g_G[(m0 + 1) * H1d + o0 + tn * 8];
        *(float4*)p0       = make_float4(lo[0], lo[1], lo[2], lo[3]);
        *(float4*)(p0 + 4) = make_float4(lo[4], lo[5], lo[6], lo[7]);
        *(float4*)p1       = make_float4(hi[0], hi[1], hi[2], hi[3]);
        *(float4*)(p1 + 4) = make_float4(hi[4], hi[5], hi[6], hi[7]);
    }
}

// ---------------------------------------------------------------------------
// Main fused kernel: M=128 rows/CTA, N=512 in 2 passes of 256, K=1024 in
// 16 chunks of 64. A = fp16 hi/lo (scaled by 64), B = fp16 single.
// 2 MMAs per k-step (ah.b + al.b). Un-scale folded into rinv.
// ---------------------------------------------------------------------------
#define SOFF_GPS   0        // 2*1024 f32 (8 KB), pre-scaled by 64
#define SOFF_B2    8192     // 512 f32
#define SOFF_WQ    10240    // 512 f32
#define SOFF_SS    12288    // 512 f32 (ss: 256 used; q partials: 512 used)
#define SOFF_RINV  14336    // 128 f32
#define SOFF_INVN  14848    // 2 f32 (scaled by 64)
#define SOFF_STG   15360
#define AHI_OFF    0        // 128 rows x 128B = 16 KB
#define ALO_OFF    16384    // 16 KB
#define BF_OFF     32768    // 256 rows x 128B = 32 KB
#define STG_BYTES  65536    // 64 KB per stage
#define SMEM_TOTAL (SOFF_STG + 2 * STG_BYTES)   // 146432 B

#define KC  64
#define NCH (H1d / KC)      // 16 chunks per pass
#define ASCALE 64.0f

__global__ void __launch_bounds__(256, 1)
k_main(const float* __restrict__ b2, const float* __restrict__ Wq,
       const float* __restrict__ bq, float* __restrict__ out) {
    extern __shared__ __align__(1024) char smem[];
    u32 sb = smem_u32(smem);
    int tid = threadIdx.x;
    int wid = tid >> 5, lane = tid & 31;
    int warp_m = wid >> 2, warp_n = wid & 3;       // 2 x 4 warp grid
    int r0 = blockIdx.x * 128, b0 = r0 >> 6;       // 2 batch rows

    float* Gps   = (float*)(smem + SOFF_GPS);
    float* b2s   = (float*)(smem + SOFF_B2);
    float* wqs   = (float*)(smem + SOFF_WQ);
    float* sss   = (float*)(smem + SOFF_SS);
    float* rinvs = (float*)(smem + SOFF_RINV);
    float* invns = (float*)(smem + SOFF_INVN);

    // Gps pre-scaled by ASCALE so generated h is 64x the true h1
    for (int i = tid; i < 2 * H1d; i += 256)
        Gps[i] = g_G[(size_t)(b0 + (i >> 10)) * H1d + (i & 1023)] * ASCALE;
    for (int i = tid; i < H2d; i += 256) { b2s[i] = b2[i]; wqs[i] = Wq[i]; }
    if (tid < 2) invns[tid] = g_invn[b0 + tid] * ASCALE;
    __syncthreads();

    // generator identity: row gm (0..127), k-half gh (0/1)
    int gm = tid & 127, gh = tid >> 7;
    int ga = gm & 63, gbl = gm >> 6;
    float inv = invns[gbl];
    const float* gpr = Gps + gbl * H1d;
    float ss = 0.f;

    // A generator: chunk c (64 k), this thread does 32 k (4 groups of 8)
    auto genA = [&](int c, int buf, bool do_ss) {
        char* stg = smem + SOFF_STG + buf * STG_BYTES;
        int ob = c * KC + gh * 32;
#pragma unroll
        for (int j4 = 0; j4 < 4; j4++) {
            int o = ob + j4 * 8;
            const float* awt = g_AWT + (size_t)o * 64 + ga;
            float h[8];
#pragma unroll
            for (int j = 0; j < 8; j++)
                h[j] = fmaxf(fmaf(inv, awt[j * 64], gpr[o + j]), 0.f);
            if (do_ss) {
                float s2 = 0.f;
#pragma unroll
                for (int j = 0; j < 8; j++) s2 = fmaf(h[j], h[j], s2);
                ss += s2;
            }
            u32 q0 = pkhf(h[0], h[1]), q1 = pkhf(h[2], h[3]);
            u32 q2 = pkhf(h[4], h[5]), q3 = pkhf(h[6], h[7]);
            u32 off = toff(gm, gh * 4 + j4);
            *(uint4*)(stg + AHI_OFF + off) = make_uint4(q0, q1, q2, q3);
            u32 l0 = pkhf(h[0] - hlo2f(q0), h[1] - hhi2f(q0));
            u32 l1 = pkhf(h[2] - hlo2f(q1), h[3] - hhi2f(q1));
            u32 l2 = pkhf(h[4] - hlo2f(q2), h[5] - hhi2f(q2));
            u32 l3 = pkhf(h[6] - hlo2f(q3), h[7] - hhi2f(q3));
            *(uint4*)(stg + ALO_OFF + off) = make_uint4(l0, l1, l2, l3);
        }
    };

    // B loader: W2 fp16, 256 n-rows x 64 k per chunk
    auto loadB = [&](int pass, int c, int buf) {
        u32 bf = sb + SOFF_STG + buf * STG_BYTES + BF_OFF;
        const __half* w2 = g_W2h + (size_t)(pass * 256) * H1d + c * KC;
#pragma unroll
        for (int i = 0; i < 8; i++) {
            int e = tid + i * 256;
            int n = e >> 3, g = e & 7;
            cpasync16(bf + toff(n, g), w2 + (size_t)n * H1d + g * 8);
        }
        asm volatile("cp.async.commit_group;" ::: "memory");
    };

    int lt = lane & 15, lh = lane >> 4;
    float qacc[8];
#pragma unroll
    for (int i = 0; i < 8; i++) qacc[i] = 0.f;

    for (int pass = 0; pass < 2; pass++) {
        float acc[4][8][4];
#pragma unroll
        for (int i = 0; i < 4; i++)
#pragma unroll
            for (int j = 0; j < 8; j++)
#pragma unroll
                for (int k = 0; k < 4; k++) acc[i][j][k] = 0.f;

        genA(0, 0, pass == 0);
        loadB(pass, 0, 0);
        asm volatile("cp.async.wait_group 0;" ::: "memory");
        __syncthreads();

        for (int c = 0; c < NCH; c++) {
            int buf = c & 1;
            if (c + 1 < NCH) {
                genA(c + 1, buf ^ 1, pass == 0);
                loadB(pass, c + 1, buf ^ 1);
            }
            u32 abase = sb + SOFF_STG + buf * STG_BYTES;
#pragma unroll
            for (int ks = 0; ks < 4; ks++) {
                int g = ks * 2 + lh;
                u32 ah[4][4], al[4][4];
#pragma unroll
                for (int mt = 0; mt < 4; mt++) {
                    int row = warp_m * 64 + mt * 16 + lt;
                    u32 off = toff(row, g);
                    ldm4(ah[mt], abase + AHI_OFF + off);
                    ldm4(al[mt], abase + ALO_OFF + off);
                }
#pragma unroll
                for (int nb = 0; nb < 4; nb++) {
                    int nrow = warp_n * 64 + nb * 16 + lt;
                    u32 off = toff(nrow, g);
                    u32 bh[4];
                    ldm4(bh, abase + BF_OFF + off);
#pragma unroll
                    for (int mt = 0; mt < 4; mt++)
#pragma unroll
                        for (int s = 0; s < 2; s++) {
                            float* cc = acc[mt][nb * 2 + s];
                            mma16816(cc, ah[mt], bh[s], bh[s + 2]);
                            mma16816(cc, al[mt], bh[s], bh[s + 2]);
                        }
                }
            }
            asm volatile("cp.async.wait_group 0;" ::: "memory");
            __syncthreads();
        }

        if (pass == 0) {
            // rinv (embeds the 1/ASCALE un-scale): acc is 64*z2_pre,
            // sqrt(ss) is 64*||h||, so acc/(sqrt(ss)+64*eps) = z2_normalized
            sss[tid] = ss;
            __syncthreads();
            if (tid < 128)
                rinvs[tid] = 1.f / (sqrtf(sss[tid] + sss[tid + 128]) +
                                    ASCALE * EPSf);
            __syncthreads();
        }

        // epilogue: q += relu(acc * rinv + b2) * Wq for this pass's 256 n
#pragma unroll
        for (int mt = 0; mt < 4; mt++) {
            int rlo = warp_m * 64 + mt * 16 + (lane >> 2);
            float rv0 = rinvs[rlo], rv1 = rinvs[rlo + 8];
#pragma unroll
            for (int nt = 0; nt < 8; nt++) {
                int n = pass * 256 + warp_n * 64 + nt * 8 + (lane & 3) * 2;
                float bb0 = b2s[n], bb1 = b2s[n + 1];
                float w0 = wqs[n], w1 = wqs[n + 1];
                const float* cc = acc[mt][nt];
                qacc[mt * 2 + 0] += fmaxf(fmaf(cc[0], rv0, bb0), 0.f) * w0 +
                                    fmaxf(fmaf(cc[1], rv0, bb1), 0.f) * w1;
                qacc[mt * 2 + 1] += fmaxf(fmaf(cc[2], rv1, bb0), 0.f) * w0 +
                                    fmaxf(fmaf(cc[3], rv1, bb1), 0.f) * w1;
            }
        }
    }

    // reduce q over the 4 lanes of each quad
#pragma unroll
    for (int off = 1; off <= 2; off <<= 1)
#pragma unroll
        for (int i = 0; i < 8; i++)
            qacc[i] += __shfl_xor_sync(0xffffffffu, qacc[i], off);

    __syncthreads();          // reuse sss for q cross-warp partials (512 f32)
    if ((lane & 3) == 0) {
#pragma unroll
        for (int mt = 0; mt < 4; mt++)
#pragma unroll
            for (int hh = 0; hh < 2; hh++) {
                int row = warp_m * 64 + mt * 16 + hh * 8 + (lane >> 2);
                sss[row * 4 + warp_n] = qacc[mt * 2 + hh];
            }
    }
    __syncthreads();
    if (tid < 128)
        out[r0 + tid] = sss[tid * 4] + sss[tid * 4 + 1] +
                        sss[tid * 4 + 2] + sss[tid * 4 + 3] + __ldg(bq);
}

// ---------------------------------------------------------------------------
extern "C" void kernel_launch(void* const* d_in, const int* in_sizes, int n_in,
                              void* d_out, int out_size) {
    const float* states = (const float*)d_in[0];
    const float* W1     = (const float*)d_in[1];
    const float* b1     = (const float*)d_in[2];
    const float* W2     = (const float*)d_in[3];
    const float* b2     = (const float*)d_in[4];
    const float* Wq     = (const float*)d_in[5];
    const float* bq     = (const float*)d_in[6];
    float* out = (float*)d_out;

    cudaFuncSetAttribute((const void*)k_main,
                         cudaFuncAttributeMaxDynamicSharedMemorySize, SMEM_TOTAL);

    k_invn<<<Bd / 8, 256>>>(states);
    k_prep<<<(H1d * Ad + H2d * H1d + 255) / 256, 256>>>(W1, W2);
    k_gemmG<<<(Bd / 128) * (H1d / 128), 256>>>(states, W1, b1);
    k_main<<<(Bd * Ad) / 128, 256, SMEM_TOTAL>>>(b2, Wq, bq, out);
}

// round 8
// speedup vs baseline: 6.0816x; 1.4048x over previous
#include <cuda_runtime.h>
#include <cuda_bf16.h>
#include <cuda_fp16.h>

#define Bd   4096
#define Sd   512
#define Ad   64
#define H1d  1024
#define H2d  512
#define EPSf 1e-8f
#define TK   16

typedef unsigned long long ull;
typedef unsigned int u32;

// ------------------------- device scratch (no allocs allowed) --------------
__device__ float g_G[Bd * H1d];              // Gp[b][o] = G*invn[b] + b1[o]
__device__ float g_AWT[H1d * Ad];            // [o][a] layout
__device__ float g_invn[Bd];
__device__ __half g_W2h[H2d * H1d];          // fp16(W2)

// ------------------------- helpers -----------------------------------------
__device__ __forceinline__ u32 smem_u32(const void* p) {
    u32 a;
    asm("{ .reg .u64 t; cvta.to.shared.u64 t, %1; cvt.u32.u64 %0, t; }"
        : "=r"(a) : "l"(p));
    return a;
}
__device__ __forceinline__ ull pk2(float lo, float hi) {
    ull r;
    asm("mov.b64 %0, {%1, %2};" : "=l"(r)
        : "r"(__float_as_uint(lo)), "r"(__float_as_uint(hi)));
    return r;
}
__device__ __forceinline__ void upk2(ull v, float& lo, float& hi) {
    unsigned a, b;
    asm("mov.b64 {%0, %1}, %2;" : "=r"(a), "=r"(b) : "l"(v));
    lo = __uint_as_float(a); hi = __uint_as_float(b);
}
__device__ __forceinline__ ull ffma2(ull a, ull b, ull c) {
    ull d;
    asm("fma.rn.f32x2 %0, %1, %2, %3;" : "=l"(d) : "l"(a), "l"(b), "l"(c));
    return d;
}
// pack two f32 into f16x2 (lo -> low 16 bits)
__device__ __forceinline__ u32 pkhf(float lo, float hi) {
    u32 r;
    asm("cvt.rn.f16x2.f32 %0, %1, %2;" : "=r"(r) : "f"(hi), "f"(lo));
    return r;
}

__device__ __forceinline__ void cpasync16(u32 dst, const void* src) {
    asm volatile("cp.async.cg.shared.global [%0], [%1], 16;"
                 :: "r"(dst), "l"(src) : "memory");
}
__device__ __forceinline__ void ldm4(u32* r, u32 addr) {
    asm volatile("ldmatrix.sync.aligned.m8n8.x4.shared.b16 {%0,%1,%2,%3}, [%4];"
                 : "=r"(r[0]), "=r"(r[1]), "=r"(r[2]), "=r"(r[3]) : "r"(addr));
}
__device__ __forceinline__ void mma16816(float* c, const u32* a, u32 b0, u32 b1) {
    asm volatile(
        "mma.sync.aligned.m16n8k16.row.col.f32.f16.f16.f32 "
        "{%0,%1,%2,%3}, {%4,%5,%6,%7}, {%8,%9}, {%0,%1,%2,%3};"
        : "+f"(c[0]), "+f"(c[1]), "+f"(c[2]), "+f"(c[3])
        : "r"(a[0]), "r"(a[1]), "r"(a[2]), "r"(a[3]), "r"(b0), "r"(b1));
}

// 128B-row SW128 tile addressing: row has 8 16B k-groups
__device__ __forceinline__ u32 toff(int row, int g) {
    return (u32)(row * 128 + ((g ^ (row & 7)) << 4));
}

// ---------------------------------------------------------------------------
// Prep (merged): AWT gather + W2 fp16 convert
// ---------------------------------------------------------------------------
__global__ void k_prep(const float* __restrict__ W1,
                       const float* __restrict__ W2) {
    int i = blockIdx.x * 256 + threadIdx.x;
    if (i < H1d * Ad) {
        int o = i >> 6, a = i & 63;
        g_AWT[i] = W1[o * 576 + 512 + a];
    }
    int j = i - H1d * Ad;
    if (j >= 0 && j < H2d * H1d) {
        g_W2h[j] = __float2half_rn(W2[j]);
    }
}
__global__ void k_invn(const float* __restrict__ states) {
    int w    = (blockIdx.x * blockDim.x + threadIdx.x) >> 5;
    int lane = threadIdx.x & 31;
    if (w >= Bd) return;
    const float* s = states + w * Sd;
    float acc = 0.f;
#pragma unroll 4
    for (int j = lane; j < Sd; j += 32) { float v = s[j]; acc += v * v; }
#pragma unroll
    for (int off = 16; off; off >>= 1) acc += __shfl_xor_sync(0xffffffffu, acc, off);
    if (lane == 0) g_invn[w] = 1.f / (sqrtf(acc + 1.f) + EPSf);
}

// ---------------------------------------------------------------------------
// Gp[b][o] = (states[b,:].W1[o,:512]) * invn[b] + b1[o]   (fp32 SIMT)
// ---------------------------------------------------------------------------
__global__ void __launch_bounds__(256) k_gemmG(const float* __restrict__ states,
                                               const float* __restrict__ W1,
                                               const float* __restrict__ b1) {
    __shared__ __align__(16) float As[2][TK][128];
    __shared__ __align__(16) float Bs[2][TK][128];

    int b0  = (blockIdx.x >> 3) * 128;
    int o0  = (blockIdx.x & 7) * 128;
    int tid = threadIdx.x;
    int tm  = tid >> 4, tn = tid & 15;

    ull acc[4][8];
#pragma unroll
    for (int i = 0; i < 4; i++)
#pragma unroll
        for (int j = 0; j < 8; j++) acc[i][j] = 0ull;

    auto loadTile = [&](int c, int buf) {
        int k0 = c * TK;
#pragma unroll
        for (int it = 0; it < 2; it++) {
            int e = tid + it * 256;
            int r = e >> 2, kq = (e & 3) * 4;
            float4 va = *(const float4*)&states[(b0 + r) * Sd + k0 + kq];
            As[buf][kq + 0][r] = va.x; As[buf][kq + 1][r] = va.y;
            As[buf][kq + 2][r] = va.z; As[buf][kq + 3][r] = va.w;
            float4 vb = *(const float4*)&W1[(o0 + r) * 576 + k0 + kq];
            Bs[buf][kq + 0][r] = vb.x; Bs[buf][kq + 1][r] = vb.y;
            Bs[buf][kq + 2][r] = vb.z; Bs[buf][kq + 3][r] = vb.w;
        }
    };

    loadTile(0, 0);
    __syncthreads();
    const int NC = Sd / TK;
    for (int c = 0; c < NC; c++) {
        int buf = c & 1;
        if (c + 1 < NC) loadTile(c + 1, buf ^ 1);
#pragma unroll
        for (int kk = 0; kk < TK; kk++) {
            ull a2[4];
            const ull* ap = (const ull*)&As[buf][kk][tm * 8];
#pragma unroll
            for (int i = 0; i < 4; i++) a2[i] = ap[i];
            float4 bv0 = *(const float4*)&Bs[buf][kk][tn * 8];
            float4 bv1 = *(const float4*)&Bs[buf][kk][tn * 8 + 4];
            ull b2r[8];
            b2r[0] = pk2(bv0.x, bv0.x); b2r[1] = pk2(bv0.y, bv0.y);
            b2r[2] = pk2(bv0.z, bv0.z); b2r[3] = pk2(bv0.w, bv0.w);
            b2r[4] = pk2(bv1.x, bv1.x); b2r[5] = pk2(bv1.y, bv1.y);
            b2r[6] = pk2(bv1.z, bv1.z); b2r[7] = pk2(bv1.w, bv1.w);
#pragma unroll
            for (int i = 0; i < 4; i++)
#pragma unroll
                for (int j = 0; j < 8; j++)
                    acc[i][j] = ffma2(a2[i], b2r[j], acc[i][j]);
        }
        __syncthreads();
    }

    float4 b1a = *(const float4*)&b1[o0 + tn * 8];
    float4 b1b = *(const float4*)&b1[o0 + tn * 8 + 4];
    float bb[8] = {b1a.x, b1a.y, b1a.z, b1a.w, b1b.x, b1b.y, b1b.z, b1b.w};
#pragma unroll
    for (int i = 0; i < 4; i++) {
        int m0 = b0 + tm * 8 + i * 2;
        float inv0 = g_invn[m0], inv1 = g_invn[m0 + 1];
        float lo[8], hi[8];
#pragma unroll
        for (int j = 0; j < 8; j++) {
            upk2(acc[i][j], lo[j], hi[j]);
            lo[j] = fmaf(lo[j], inv0, bb[j]);
            hi[j] = fmaf(hi[j], inv1, bb[j]);
        }
        float* p0 = &g_G[(m0 + 0) * H1d + o0 + tn * 8];
        float* p1 = &g_G[(m0 + 1) * H1d + o0 + tn * 8];
        *(float4*)p0       = make_float4(lo[0], lo[1], lo[2], lo[3]);
        *(float4*)(p0 + 4) = make_float4(lo[4], lo[5], lo[6], lo[7]);
        *(float4*)p1       = make_float4(hi[0], hi[1], hi[2], hi[3]);
        *(float4*)(p1 + 4) = make_float4(hi[4], hi[5], hi[6], hi[7]);
    }
}

// ---------------------------------------------------------------------------
// Main fused kernel: M=128 rows/CTA, N=512 in 2 passes of 256, K=1024 in
// 16 chunks of 64. A = single fp16 (scaled by 64), B = fp16.
// 1 MMA per k-step; A-generation interleaved into the MMA stream.
// ---------------------------------------------------------------------------
#define SOFF_GPS   0        // 2*1024 f32 (8 KB), pre-scaled by 64
#define SOFF_B2    8192     // 512 f32
#define SOFF_WQ    10240    // 512 f32
#define SOFF_SS    12288    // 512 f32 (ss: 256 used; q partials: 512 used)
#define SOFF_RINV  14336    // 128 f32
#define SOFF_INVN  14848    // 2 f32 (scaled by 64)
#define SOFF_STG   15360
#define AF_OFF     0        // 128 rows x 128B = 16 KB
#define BF_OFF     16384    // 256 rows x 128B = 32 KB
#define STG_BYTES  49152    // 48 KB per stage
#define SMEM_TOTAL (SOFF_STG + 2 * STG_BYTES)   // 113664 B

#define KC  64
#define NCH (H1d / KC)      // 16 chunks per pass
#define ASCALE 64.0f

__global__ void __launch_bounds__(256, 1)
k_main(const float* __restrict__ b2, const float* __restrict__ Wq,
       const float* __restrict__ bq, float* __restrict__ out) {
    extern __shared__ __align__(1024) char smem[];
    u32 sb = smem_u32(smem);
    int tid = threadIdx.x;
    int wid = tid >> 5, lane = tid & 31;
    int warp_m = wid >> 2, warp_n = wid & 3;       // 2 x 4 warp grid
    int r0 = blockIdx.x * 128, b0 = r0 >> 6;       // 2 batch rows

    float* Gps   = (float*)(smem + SOFF_GPS);
    float* b2s   = (float*)(smem + SOFF_B2);
    float* wqs   = (float*)(smem + SOFF_WQ);
    float* sss   = (float*)(smem + SOFF_SS);
    float* rinvs = (float*)(smem + SOFF_RINV);
    float* invns = (float*)(smem + SOFF_INVN);

    // Gps pre-scaled by ASCALE so generated h is 64x the true h1
    for (int i = tid; i < 2 * H1d; i += 256)
        Gps[i] = g_G[(size_t)(b0 + (i >> 10)) * H1d + (i & 1023)] * ASCALE;
    for (int i = tid; i < H2d; i += 256) { b2s[i] = b2[i]; wqs[i] = Wq[i]; }
    if (tid < 2) invns[tid] = g_invn[b0 + tid] * ASCALE;
    __syncthreads();

    // generator identity: row gm (0..127), k-half gh (0/1)
    int gm = tid & 127, gh = tid >> 7;
    int ga = gm & 63, gbl = gm >> 6;
    float inv = invns[gbl];
    const float* gpr = Gps + gbl * H1d;
    float ss = 0.f;

    // A generator piece: 8 k-values (group j4 of this thread's 32 k)
    auto genAp = [&](int c, int buf, int j4, bool do_ss) {
        char* stg = smem + SOFF_STG + buf * STG_BYTES;
        int o = c * KC + gh * 32 + j4 * 8;
        const float* awt = g_AWT + (size_t)o * 64 + ga;
        float h[8];
#pragma unroll
        for (int j = 0; j < 8; j++)
            h[j] = fmaxf(fmaf(inv, awt[j * 64], gpr[o + j]), 0.f);
        if (do_ss) {
            float s2 = 0.f;
#pragma unroll
            for (int j = 0; j < 8; j++) s2 = fmaf(h[j], h[j], s2);
            ss += s2;
        }
        u32 q0 = pkhf(h[0], h[1]), q1 = pkhf(h[2], h[3]);
        u32 q2 = pkhf(h[4], h[5]), q3 = pkhf(h[6], h[7]);
        u32 off = toff(gm, gh * 4 + j4);
        *(uint4*)(stg + AF_OFF + off) = make_uint4(q0, q1, q2, q3);
    };

    // B loader: W2 fp16, 256 n-rows x 64 k per chunk
    auto loadB = [&](int pass, int c, int buf) {
        u32 bf = sb + SOFF_STG + buf * STG_BYTES + BF_OFF;
        const __half* w2 = g_W2h + (size_t)(pass * 256) * H1d + c * KC;
#pragma unroll
        for (int i = 0; i < 8; i++) {
            int e = tid + i * 256;
            int n = e >> 3, g = e & 7;
            cpasync16(bf + toff(n, g), w2 + (size_t)n * H1d + g * 8);
        }
        asm volatile("cp.async.commit_group;" ::: "memory");
    };

    int lt = lane & 15, lh = lane >> 4;
    float qacc[8];
#pragma unroll
    for (int i = 0; i < 8; i++) qacc[i] = 0.f;

    for (int pass = 0; pass < 2; pass++) {
        float acc[4][8][4];
#pragma unroll
        for (int i = 0; i < 4; i++)
#pragma unroll
            for (int j = 0; j < 8; j++)
#pragma unroll
                for (int k = 0; k < 4; k++) acc[i][j][k] = 0.f;

        // prologue: chunk 0
#pragma unroll
        for (int j4 = 0; j4 < 4; j4++) genAp(0, 0, j4, pass == 0);
        loadB(pass, 0, 0);
        asm volatile("cp.async.wait_group 0;" ::: "memory");
        __syncthreads();

        for (int c = 0; c < NCH; c++) {
            int buf = c & 1;
            bool more = (c + 1 < NCH);
            if (more) loadB(pass, c + 1, buf ^ 1);

            u32 abase = sb + SOFF_STG + buf * STG_BYTES;
#pragma unroll
            for (int ks = 0; ks < 4; ks++) {
                // interleave: generate one piece of next chunk's A tile
                if (more) genAp(c + 1, buf ^ 1, ks, pass == 0);

                int g = ks * 2 + lh;
                u32 ah[4][4];
#pragma unroll
                for (int mt = 0; mt < 4; mt++) {
                    int row = warp_m * 64 + mt * 16 + lt;
                    ldm4(ah[mt], abase + AF_OFF + toff(row, g));
                }
#pragma unroll
                for (int nb = 0; nb < 4; nb++) {
                    int nrow = warp_n * 64 + nb * 16 + lt;
                    u32 bh[4];
                    ldm4(bh, abase + BF_OFF + toff(nrow, g));
#pragma unroll
                    for (int mt = 0; mt < 4; mt++)
#pragma unroll
                        for (int s = 0; s < 2; s++)
                            mma16816(acc[mt][nb * 2 + s], ah[mt],
                                     bh[s], bh[s + 2]);
                }
            }
            asm volatile("cp.async.wait_group 0;" ::: "memory");
            __syncthreads();
        }

        if (pass == 0) {
            // rinv embeds the 1/ASCALE un-scale: acc = 64*z2_pre,
            // sqrt(ss) = 64*||h||  =>  acc * rinv = z2_normalized
            sss[tid] = ss;
            __syncthreads();
            if (tid < 128)
                rinvs[tid] = 1.f / (sqrtf(sss[tid] + sss[tid + 128]) +
                                    ASCALE * EPSf);
            __syncthreads();
        }

        // epilogue: q += relu(acc * rinv + b2) * Wq for this pass's 256 n
#pragma unroll
        for (int mt = 0; mt < 4; mt++) {
            int rlo = warp_m * 64 + mt * 16 + (lane >> 2);
            float rv0 = rinvs[rlo], rv1 = rinvs[rlo + 8];
#pragma unroll
            for (int nt = 0; nt < 8; nt++) {
                int n = pass * 256 + warp_n * 64 + nt * 8 + (lane & 3) * 2;
                float bb0 = b2s[n], bb1 = b2s[n + 1];
                float w0 = wqs[n], w1 = wqs[n + 1];
                const float* cc = acc[mt][nt];
                qacc[mt * 2 + 0] += fmaxf(fmaf(cc[0], rv0, bb0), 0.f) * w0 +
                                    fmaxf(fmaf(cc[1], rv0, bb1), 0.f) * w1;
                qacc[mt * 2 + 1] += fmaxf(fmaf(cc[2], rv1, bb0), 0.f) * w0 +
                                    fmaxf(fmaf(cc[3], rv1, bb1), 0.f) * w1;
            }
        }
    }

    // reduce q over the 4 lanes of each quad
#pragma unroll
    for (int off = 1; off <= 2; off <<= 1)
#pragma unroll
        for (int i = 0; i < 8; i++)
            qacc[i] += __shfl_xor_sync(0xffffffffu, qacc[i], off);

    __syncthreads();          // reuse sss for q cross-warp partials (512 f32)
    if ((lane & 3) == 0) {
#pragma unroll
        for (int mt = 0; mt < 4; mt++)
#pragma unroll
            for (int hh = 0; hh < 2; hh++) {
                int row = warp_m * 64 + mt * 16 + hh * 8 + (lane >> 2);
                sss[row * 4 + warp_n] = qacc[mt * 2 + hh];
            }
    }
    __syncthreads();
    if (tid < 128)
        out[r0 + tid] = sss[tid * 4] + sss[tid * 4 + 1] +
                        sss[tid * 4 + 2] + sss[tid * 4 + 3] + __ldg(bq);
}

// ---------------------------------------------------------------------------
extern "C" void kernel_launch(void* const* d_in, const int* in_sizes, int n_in,
                              void* d_out, int out_size) {
    const float* states = (const float*)d_in[0];
    const float* W1     = (const float*)d_in[1];
    const float* b1     = (const float*)d_in[2];
    const float* W2     = (const float*)d_in[3];
    const float* b2     = (const float*)d_in[4];
    const float* Wq     = (const float*)d_in[5];
    const float* bq     = (const float*)d_in[6];
    float* out = (float*)d_out;

    cudaFuncSetAttribute((const void*)k_main,
                         cudaFuncAttributeMaxDynamicSharedMemorySize, SMEM_TOTAL);

    k_invn<<<Bd / 8, 256>>>(states);
    k_prep<<<(H1d * Ad + H2d * H1d + 255) / 256, 256>>>(W1, W2);
    k_gemmG<<<(Bd / 128) * (H1d / 128), 256>>>(states, W1, b1);
    k_main<<<(Bd * Ad) / 128, 256, SMEM_TOTAL>>>(b2, Wq, bq, out);
}

// round 9
// speedup vs baseline: 7.7735x; 1.2782x over previous
#include <cuda_runtime.h>
#include <cuda_bf16.h>
#include <cuda_fp16.h>

#define Bd   4096
#define Sd   512
#define Ad   64
#define H1d  1024
#define H2d  512
#define EPSf 1e-8f
#define TK   16

typedef unsigned long long ull;
typedef unsigned int u32;

// ------------------------- device scratch (no allocs allowed) --------------
__device__ float g_G[Bd * H1d];              // Gp[b][o] = G*invn[b] + b1[o]
__device__ float g_AWT[H1d * Ad];            // [o][a] layout
__device__ float g_invn[Bd];
__device__ __half g_W2h[H2d * H1d];          // fp16(W2)

// ------------------------- helpers -----------------------------------------
__device__ __forceinline__ u32 smem_u32(const void* p) {
    u32 a;
    asm("{ .reg .u64 t; cvta.to.shared.u64 t, %1; cvt.u32.u64 %0, t; }"
        : "=r"(a) : "l"(p));
    return a;
}
__device__ __forceinline__ ull pk2(float lo, float hi) {
    ull r;
    asm("mov.b64 %0, {%1, %2};" : "=l"(r)
        : "r"(__float_as_uint(lo)), "r"(__float_as_uint(hi)));
    return r;
}
__device__ __forceinline__ void upk2(ull v, float& lo, float& hi) {
    unsigned a, b;
    asm("mov.b64 {%0, %1}, %2;" : "=r"(a), "=r"(b) : "l"(v));
    lo = __uint_as_float(a); hi = __uint_as_float(b);
}
__device__ __forceinline__ ull ffma2(ull a, ull b, ull c) {
    ull d;
    asm("fma.rn.f32x2 %0, %1, %2, %3;" : "=l"(d) : "l"(a), "l"(b), "l"(c));
    return d;
}
// pack two f32 into f16x2 (lo -> low 16 bits)
__device__ __forceinline__ u32 pkhf(float lo, float hi) {
    u32 r;
    asm("cvt.rn.f16x2.f32 %0, %1, %2;" : "=r"(r) : "f"(hi), "f"(lo));
    return r;
}

__device__ __forceinline__ void cpasync16(u32 dst, const void* src) {
    asm volatile("cp.async.cg.shared.global [%0], [%1], 16;"
                 :: "r"(dst), "l"(src) : "memory");
}
__device__ __forceinline__ void ldm4(u32* r, u32 addr) {
    asm volatile("ldmatrix.sync.aligned.m8n8.x4.shared.b16 {%0,%1,%2,%3}, [%4];"
                 : "=r"(r[0]), "=r"(r[1]), "=r"(r[2]), "=r"(r[3]) : "r"(addr));
}
__device__ __forceinline__ void mma16816(float* c, const u32* a, u32 b0, u32 b1) {
    asm volatile(
        "mma.sync.aligned.m16n8k16.row.col.f32.f16.f16.f32 "
        "{%0,%1,%2,%3}, {%4,%5,%6,%7}, {%8,%9}, {%0,%1,%2,%3};"
        : "+f"(c[0]), "+f"(c[1]), "+f"(c[2]), "+f"(c[3])
        : "r"(a[0]), "r"(a[1]), "r"(a[2]), "r"(a[3]), "r"(b0), "r"(b1));
}

// 128B-row SW128 tile addressing: row has 8 16B k-groups
__device__ __forceinline__ u32 toff(int row, int g) {
    return (u32)(row * 128 + ((g ^ (row & 7)) << 4));
}

// ---------------------------------------------------------------------------
// Prep (merged): AWT gather + W2 fp16 convert
// ---------------------------------------------------------------------------
__global__ void k_prep(const float* __restrict__ W1,
                       const float* __restrict__ W2) {
    int i = blockIdx.x * 256 + threadIdx.x;
    if (i < H1d * Ad) {
        int o = i >> 6, a = i & 63;
        g_AWT[i] = W1[o * 576 + 512 + a];
    }
    int j = i - H1d * Ad;
    if (j >= 0 && j < H2d * H1d) {
        g_W2h[j] = __float2half_rn(W2[j]);
    }
}
__global__ void k_invn(const float* __restrict__ states) {
    int w    = (blockIdx.x * blockDim.x + threadIdx.x) >> 5;
    int lane = threadIdx.x & 31;
    if (w >= Bd) return;
    const float* s = states + w * Sd;
    float acc = 0.f;
#pragma unroll 4
    for (int j = lane; j < Sd; j += 32) { float v = s[j]; acc += v * v; }
#pragma unroll
    for (int off = 16; off; off >>= 1) acc += __shfl_xor_sync(0xffffffffu, acc, off);
    if (lane == 0) g_invn[w] = 1.f / (sqrtf(acc + 1.f) + EPSf);
}

// ---------------------------------------------------------------------------
// Gp[b][o] = (states[b,:].W1[o,:512]) * invn[b] + b1[o]   (fp32 SIMT)
// ---------------------------------------------------------------------------
__global__ void __launch_bounds__(256) k_gemmG(const float* __restrict__ states,
                                               const float* __restrict__ W1,
                                               const float* __restrict__ b1) {
    __shared__ __align__(16) float As[2][TK][128];
    __shared__ __align__(16) float Bs[2][TK][128];

    int b0  = (blockIdx.x >> 3) * 128;
    int o0  = (blockIdx.x & 7) * 128;
    int tid = threadIdx.x;
    int tm  = tid >> 4, tn = tid & 15;

    ull acc[4][8];
#pragma unroll
    for (int i = 0; i < 4; i++)
#pragma unroll
        for (int j = 0; j < 8; j++) acc[i][j] = 0ull;

    auto loadTile = [&](int c, int buf) {
        int k0 = c * TK;
#pragma unroll
        for (int it = 0; it < 2; it++) {
            int e = tid + it * 256;
            int r = e >> 2, kq = (e & 3) * 4;
            float4 va = *(const float4*)&states[(b0 + r) * Sd + k0 + kq];
            As[buf][kq + 0][r] = va.x; As[buf][kq + 1][r] = va.y;
            As[buf][kq + 2][r] = va.z; As[buf][kq + 3][r] = va.w;
            float4 vb = *(const float4*)&W1[(o0 + r) * 576 + k0 + kq];
            Bs[buf][kq + 0][r] = vb.x; Bs[buf][kq + 1][r] = vb.y;
            Bs[buf][kq + 2][r] = vb.z; Bs[buf][kq + 3][r] = vb.w;
        }
    };

    loadTile(0, 0);
    __syncthreads();
    const int NC = Sd / TK;
    for (int c = 0; c < NC; c++) {
        int buf = c & 1;
        if (c + 1 < NC) loadTile(c + 1, buf ^ 1);
#pragma unroll
        for (int kk = 0; kk < TK; kk++) {
            ull a2[4];
            const ull* ap = (const ull*)&As[buf][kk][tm * 8];
#pragma unroll
            for (int i = 0; i < 4; i++) a2[i] = ap[i];
            float4 bv0 = *(const float4*)&Bs[buf][kk][tn * 8];
            float4 bv1 = *(const float4*)&Bs[buf][kk][tn * 8 + 4];
            ull b2r[8];
            b2r[0] = pk2(bv0.x, bv0.x); b2r[1] = pk2(bv0.y, bv0.y);
            b2r[2] = pk2(bv0.z, bv0.z); b2r[3] = pk2(bv0.w, bv0.w);
            b2r[4] = pk2(bv1.x, bv1.x); b2r[5] = pk2(bv1.y, bv1.y);
            b2r[6] = pk2(bv1.z, bv1.z); b2r[7] = pk2(bv1.w, bv1.w);
#pragma unroll
            for (int i = 0; i < 4; i++)
#pragma unroll
                for (int j = 0; j < 8; j++)
                    acc[i][j] = ffma2(a2[i], b2r[j], acc[i][j]);
        }
        __syncthreads();
    }

    float4 b1a = *(const float4*)&b1[o0 + tn * 8];
    float4 b1b = *(const float4*)&b1[o0 + tn * 8 + 4];
    float bb[8] = {b1a.x, b1a.y, b1a.z, b1a.w, b1b.x, b1b.y, b1b.z, b1b.w};
#pragma unroll
    for (int i = 0; i < 4; i++) {
        int m0 = b0 + tm * 8 + i * 2;
        float inv0 = g_invn[m0], inv1 = g_invn[m0 + 1];
        float lo[8], hi[8];
#pragma unroll
        for (int j = 0; j < 8; j++) {
            upk2(acc[i][j], lo[j], hi[j]);
            lo[j] = fmaf(lo[j], inv0, bb[j]);
            hi[j] = fmaf(hi[j], inv1, bb[j]);
        }
        float* p0 = &g_G[(m0 + 0) * H1d + o0 + tn * 8];
        float* p1 = &g_G[(m0 + 1) * H1d + o0 + tn * 8];
        *(float4*)p0       = make_float4(lo[0], lo[1], lo[2], lo[3]);
        *(float4*)(p0 + 4) = make_float4(lo[4], lo[5], lo[6], lo[7]);
        *(float4*)p1       = make_float4(hi[0], hi[1], hi[2], hi[3]);
        *(float4*)(p1 + 4) = make_float4(hi[4], hi[5], hi[6], hi[7]);
    }
}

// ---------------------------------------------------------------------------
// Main fused kernel: M=64 rows/CTA (1 batch x 64 actions), N=512 in 2 passes
// of 256, K=1024 in 16 chunks of 64. A = single fp16 (scaled by 64), B = fp16.
// 2 CTAs/SM (128-reg cap) for latency hiding.
// ---------------------------------------------------------------------------
#define SOFF_GPS   0        // 1024 f32 (4 KB), pre-scaled by 64
#define SOFF_B2    4096     // 512 f32
#define SOFF_WQ    6144     // 512 f32
#define SOFF_SS    8192     // 256 f32 (ss; reused for q cross-warp partials)
#define SOFF_RINV  9216     // 64 f32
#define SOFF_STG   10240
#define AF_OFF     0        // 64 rows x 128B = 8 KB
#define BF_OFF     8192     // 256 rows x 128B = 32 KB
#define STG_BYTES  40960    // 40 KB per stage
#define SMEM_TOTAL (SOFF_STG + 2 * STG_BYTES)   // 92160 B -> 2 CTAs = 180 KB

#define KC  64
#define NCH (H1d / KC)      // 16 chunks per pass
#define ASCALE 64.0f

__global__ void __launch_bounds__(256, 2)
k_main(const float* __restrict__ b2, const float* __restrict__ Wq,
       const float* __restrict__ bq, float* __restrict__ out) {
    extern __shared__ __align__(1024) char smem[];
    u32 sb = smem_u32(smem);
    int tid = threadIdx.x;
    int wid = tid >> 5, lane = tid & 31;
    int warp_m = wid >> 2, warp_n = wid & 3;       // 2 x 4 warp grid
    int bidx = blockIdx.x;                          // 1 batch row per CTA
    int r0 = bidx * 64;

    float* Gps   = (float*)(smem + SOFF_GPS);
    float* b2s   = (float*)(smem + SOFF_B2);
    float* wqs   = (float*)(smem + SOFF_WQ);
    float* sss   = (float*)(smem + SOFF_SS);
    float* rinvs = (float*)(smem + SOFF_RINV);

    // Gps pre-scaled by ASCALE so generated h is 64x the true h1
    float inv = g_invn[bidx] * ASCALE;
    for (int i = tid; i < H1d; i += 256)
        Gps[i] = g_G[(size_t)bidx * H1d + i] * ASCALE;
    for (int i = tid; i < H2d; i += 256) { b2s[i] = b2[i]; wqs[i] = Wq[i]; }
    __syncthreads();

    // generator identity: row gm (0..63 = action), k-group pair gq2 (0..3)
    int gm = tid & 63, gq2 = tid >> 6;
    float ss = 0.f;

    // A generator piece: 8 k-values (group g = gq2*2 + piece)
    auto genAp = [&](int c, int buf, int piece, bool do_ss) {
        char* stg = smem + SOFF_STG + buf * STG_BYTES;
        int g = gq2 * 2 + piece;
        int o = c * KC + g * 8;
        const float* awt = g_AWT + (size_t)o * 64 + gm;
        float h[8];
#pragma unroll
        for (int j = 0; j < 8; j++)
            h[j] = fmaxf(fmaf(inv, awt[j * 64], Gps[o + j]), 0.f);
        if (do_ss) {
            float s2 = 0.f;
#pragma unroll
            for (int j = 0; j < 8; j++) s2 = fmaf(h[j], h[j], s2);
            ss += s2;
        }
        u32 q0 = pkhf(h[0], h[1]), q1 = pkhf(h[2], h[3]);
        u32 q2 = pkhf(h[4], h[5]), q3 = pkhf(h[6], h[7]);
        *(uint4*)(stg + AF_OFF + toff(gm, g)) = make_uint4(q0, q1, q2, q3);
    };

    // B loader: W2 fp16, 256 n-rows x 64 k per chunk
    auto loadB = [&](int pass, int c, int buf) {
        u32 bf = sb + SOFF_STG + buf * STG_BYTES + BF_OFF;
        const __half* w2 = g_W2h + (size_t)(pass * 256) * H1d + c * KC;
#pragma unroll
        for (int i = 0; i < 8; i++) {
            int e = tid + i * 256;
            int n = e >> 3, g = e & 7;
            cpasync16(bf + toff(n, g), w2 + (size_t)n * H1d + g * 8);
        }
        asm volatile("cp.async.commit_group;" ::: "memory");
    };

    int lt = lane & 15, lh = lane >> 4;
    float qacc[4] = {0.f, 0.f, 0.f, 0.f};

    for (int pass = 0; pass < 2; pass++) {
        float acc[2][8][4];
#pragma unroll
        for (int i = 0; i < 2; i++)
#pragma unroll
            for (int j = 0; j < 8; j++)
#pragma unroll
                for (int k = 0; k < 4; k++) acc[i][j][k] = 0.f;

        // prologue: chunk 0
        genAp(0, 0, 0, pass == 0);
        genAp(0, 0, 1, pass == 0);
        loadB(pass, 0, 0);
        asm volatile("cp.async.wait_group 0;" ::: "memory");
        __syncthreads();

        for (int c = 0; c < NCH; c++) {
            int buf = c & 1;
            bool more = (c + 1 < NCH);
            if (more) loadB(pass, c + 1, buf ^ 1);

            u32 abase = sb + SOFF_STG + buf * STG_BYTES;
#pragma unroll
            for (int ks = 0; ks < 4; ks++) {
                // interleave: generate next chunk's A tile (2 pieces)
                if (more && (ks & 1) == 0)
                    genAp(c + 1, buf ^ 1, ks >> 1, pass == 0);

                int g = ks * 2 + lh;
                u32 ah[2][4];
#pragma unroll
                for (int mt = 0; mt < 2; mt++) {
                    int row = warp_m * 32 + mt * 16 + lt;
                    ldm4(ah[mt], abase + AF_OFF + toff(row, g));
                }
#pragma unroll
                for (int nb = 0; nb < 4; nb++) {
                    int nrow = warp_n * 64 + nb * 16 + lt;
                    u32 bh[4];
                    ldm4(bh, abase + BF_OFF + toff(nrow, g));
#pragma unroll
                    for (int mt = 0; mt < 2; mt++)
#pragma unroll
                        for (int s = 0; s < 2; s++)
                            mma16816(acc[mt][nb * 2 + s], ah[mt],
                                     bh[s], bh[s + 2]);
                }
            }
            asm volatile("cp.async.wait_group 0;" ::: "memory");
            __syncthreads();
        }

        if (pass == 0) {
            // rinv embeds the 1/ASCALE un-scale: acc = 64*z2_pre,
            // sqrt(ss) = 64*||h||  =>  acc * rinv = z2_normalized
            sss[tid] = ss;
            __syncthreads();
            if (tid < 64)
                rinvs[tid] = 1.f / (sqrtf(sss[tid] + sss[tid + 64] +
                                          sss[tid + 128] + sss[tid + 192]) +
                                    ASCALE * EPSf);
            __syncthreads();
        }

        // epilogue: q += relu(acc * rinv + b2) * Wq for this pass's 256 n
#pragma unroll
        for (int mt = 0; mt < 2; mt++) {
            int rlo = warp_m * 32 + mt * 16 + (lane >> 2);
            float rv0 = rinvs[rlo], rv1 = rinvs[rlo + 8];
#pragma unroll
            for (int nt = 0; nt < 8; nt++) {
                int n = pass * 256 + warp_n * 64 + nt * 8 + (lane & 3) * 2;
                float bb0 = b2s[n], bb1 = b2s[n + 1];
                float w0 = wqs[n], w1 = wqs[n + 1];
                const float* cc = acc[mt][nt];
                qacc[mt * 2 + 0] += fmaxf(fmaf(cc[0], rv0, bb0), 0.f) * w0 +
                                    fmaxf(fmaf(cc[1], rv0, bb1), 0.f) * w1;
                qacc[mt * 2 + 1] += fmaxf(fmaf(cc[2], rv1, bb0), 0.f) * w0 +
                                    fmaxf(fmaf(cc[3], rv1, bb1), 0.f) * w1;
            }
        }
    }

    // reduce q over the 4 lanes of each quad
#pragma unroll
    for (int off = 1; off <= 2; off <<= 1)
#pragma unroll
        for (int i = 0; i < 4; i++)
            qacc[i] += __shfl_xor_sync(0xffffffffu, qacc[i], off);

    __syncthreads();          // reuse sss for q cross-warp partials (256 f32)
    if ((lane & 3) == 0) {
#pragma unroll
        for (int mt = 0; mt < 2; mt++)
#pragma unroll
            for (int hh = 0; hh < 2; hh++) {
                int row = warp_m * 32 + mt * 16 + hh * 8 + (lane >> 2);
                sss[row * 4 + warp_n] = qacc[mt * 2 + hh];
            }
    }
    __syncthreads();
    if (tid < 64)
        out[r0 + tid] = sss[tid * 4] + sss[tid * 4 + 1] +
                        sss[tid * 4 + 2] + sss[tid * 4 + 3] + __ldg(bq);
}

// ---------------------------------------------------------------------------
extern "C" void kernel_launch(void* const* d_in, const int* in_sizes, int n_in,
                              void* d_out, int out_size) {
    const float* states = (const float*)d_in[0];
    const float* W1     = (const float*)d_in[1];
    const float* b1     = (const float*)d_in[2];
    const float* W2     = (const float*)d_in[3];
    const float* b2     = (const float*)d_in[4];
    const float* Wq     = (const float*)d_in[5];
    const float* bq     = (const float*)d_in[6];
    float* out = (float*)d_out;

    cudaFuncSetAttribute((const void*)k_main,
                         cudaFuncAttributeMaxDynamicSharedMemorySize, SMEM_TOTAL);

    k_invn<<<Bd / 8, 256>>>(states);
    k_prep<<<(H1d * Ad + H2d * H1d + 255) / 256, 256>>>(W1, W2);
    k_gemmG<<<(Bd / 128) * (H1d / 128), 256>>>(states, W1, b1);
    k_main<<<Bd, 256, SMEM_TOTAL>>>(b2, Wq, bq, out);
}